// round 2
// baseline (speedup 1.0000x reference)
#include <cuda_runtime.h>

// ---------------------------------------------------------------------------
// update_e: SchNet CFConv edge message
//   C    = 0.5*(cos(pi*d/10)+1)
//   h    = softplus(dist_emb @ mlp1_w^T + b1) - log(2)
//   W    = (h @ mlp2_w^T + b2) * C
//   out  = (v @ lin_w^T)[j] * W
//
// R1 fix: edge_index is int32 (JAX x64 disabled downcasts int64 -> int32).
// fp32 FFMA baseline:
//   Kernel A: vl = v @ lin_w^T  -> __device__ scratch (25.6 MB, L2-resident)
//   Kernel B: fused per-edge-tile double GEMM + epilogue.
//     block = 256 threads (16x16), tile = 128 edges x 128 feats,
//     8x8 register micro-tile, weights + tiles in SMEM (~187 KB, 1 CTA/SM).
// ---------------------------------------------------------------------------

#define SHIFT_LN2       0.69314718055994530942f
#define PI_OVER_CUTOFF  0.31415926535897932385f   // pi / 10

__device__ float g_vl[50000 * 128];

extern __shared__ float smem[];

__device__ __forceinline__ float softplus_fast(float x) {
    // log(1+e^x); for x>15 the correction is < 3e-7
    return (x > 15.f) ? x : __logf(1.f + __expf(x));
}

// ------------------------- Kernel A: vl = v @ lin_w^T -----------------------
__global__ void __launch_bounds__(256, 1)
vl_kernel(const float* __restrict__ v, const float* __restrict__ lin_w, int nrows)
{
    float* wT = smem;               // [128][128]  wT[k][f] = lin_w[f][k]
    float* a  = smem + 128 * 128;   // [128][132]  v rows (padded)
    const int tid = threadIdx.x;
    const int r0  = blockIdx.x * 128;

    for (int i = tid; i < 128 * 128; i += 256) {
        int f = i >> 7, k = i & 127;
        wT[k * 128 + f] = lin_w[i];
    }
    for (int i = tid; i < 128 * 128; i += 256) {
        int r = i >> 7, k = i & 127;
        int rg = r0 + r;
        a[r * 132 + k] = (rg < nrows) ? v[(size_t)rg * 128 + k] : 0.f;
    }
    __syncthreads();

    const int tx = tid & 15, ty = tid >> 4;
    const int f0 = tx * 8, rr0 = ty * 8;

    float acc[8][8];
    #pragma unroll
    for (int i = 0; i < 8; i++)
        #pragma unroll
        for (int j = 0; j < 8; j++) acc[i][j] = 0.f;

    #pragma unroll 8
    for (int k = 0; k < 128; k++) {
        float4 b0 = *reinterpret_cast<const float4*>(&wT[k * 128 + f0]);
        float4 b1 = *reinterpret_cast<const float4*>(&wT[k * 128 + f0 + 4]);
        #pragma unroll
        for (int i = 0; i < 8; i++) {
            float av = a[(rr0 + i) * 132 + k];
            acc[i][0] += av * b0.x; acc[i][1] += av * b0.y;
            acc[i][2] += av * b0.z; acc[i][3] += av * b0.w;
            acc[i][4] += av * b1.x; acc[i][5] += av * b1.y;
            acc[i][6] += av * b1.z; acc[i][7] += av * b1.w;
        }
    }

    #pragma unroll
    for (int i = 0; i < 8; i++) {
        int rg = r0 + rr0 + i;
        if (rg < nrows) {
            float4 o0 = make_float4(acc[i][0], acc[i][1], acc[i][2], acc[i][3]);
            float4 o1 = make_float4(acc[i][4], acc[i][5], acc[i][6], acc[i][7]);
            *reinterpret_cast<float4*>(&g_vl[(size_t)rg * 128 + f0])     = o0;
            *reinterpret_cast<float4*>(&g_vl[(size_t)rg * 128 + f0 + 4]) = o1;
        }
    }
}

// --------------------- Kernel B: fused edge tile kernel ---------------------
__global__ void __launch_bounds__(256, 1)
edge_kernel(const float* __restrict__ dist,
            const float* __restrict__ dist_emb,
            const int* __restrict__ edge_index,   // int32! row 0 = source nodes
            const float* __restrict__ mlp1_w, const float* __restrict__ mlp1_b,
            const float* __restrict__ mlp2_w, const float* __restrict__ mlp2_b,
            float* __restrict__ out, int E)
{
    float* w1T = smem;                     // [50][128]   w1T[g][f] = mlp1_w[f][g]
    float* w2T = w1T + 50 * 128;           // [128][128]  w2T[k][f] = mlp2_w[f][k]
    float* b1s = w2T + 128 * 128;          // [128]
    float* b2s = b1s + 128;                // [128]
    float* Cs  = b2s + 128;                // [128] cosine cutoff per edge
    float* emb = Cs + 128;                 // [128][52]   emb tile (padded)
    float* hs  = emb + 128 * 52;           // [128][132]  h tile (padded)
    int*   js  = (int*)(hs + 128 * 132);   // [128] source node per edge

    const int tid = threadIdx.x;
    const long long e0 = (long long)blockIdx.x * 128;

    // ---- stage tile + weights into SMEM ----
    for (int i = tid; i < 50 * 128; i += 256) {
        int f = i / 50, g = i - f * 50;
        w1T[g * 128 + f] = mlp1_w[i];
    }
    for (int i = tid; i < 128 * 128; i += 256) {
        int f = i >> 7, k = i & 127;
        w2T[k * 128 + f] = mlp2_w[i];
    }
    if (tid < 128) {
        b1s[tid] = mlp1_b[tid];
        b2s[tid] = mlp2_b[tid];
        long long e = e0 + tid;
        if (e < E) {
            float d = dist[e];
            Cs[tid] = 0.5f * (__cosf(d * PI_OVER_CUTOFF) + 1.f);
            js[tid] = edge_index[e];        // row 0 (source), int32
        } else {
            Cs[tid] = 0.f;
            js[tid] = 0;
        }
    }
    for (int i = tid; i < 128 * 50; i += 256) {
        int el = i / 50, g = i - el * 50;
        long long e = e0 + el;
        emb[el * 52 + g] = (e < E) ? dist_emb[e * 50 + g] : 0.f;
    }
    __syncthreads();

    const int tx = tid & 15, ty = tid >> 4;
    const int f0 = tx * 8, er0 = ty * 8;

    // ---- stage 1: acc = emb_tile @ w1T  (K = 50) ----
    float acc[8][8];
    #pragma unroll
    for (int i = 0; i < 8; i++)
        #pragma unroll
        for (int j = 0; j < 8; j++) acc[i][j] = 0.f;

    #pragma unroll 5
    for (int g = 0; g < 50; g++) {
        float4 b0 = *reinterpret_cast<const float4*>(&w1T[g * 128 + f0]);
        float4 b1 = *reinterpret_cast<const float4*>(&w1T[g * 128 + f0 + 4]);
        #pragma unroll
        for (int i = 0; i < 8; i++) {
            float av = emb[(er0 + i) * 52 + g];
            acc[i][0] += av * b0.x; acc[i][1] += av * b0.y;
            acc[i][2] += av * b0.z; acc[i][3] += av * b0.w;
            acc[i][4] += av * b1.x; acc[i][5] += av * b1.y;
            acc[i][6] += av * b1.z; acc[i][7] += av * b1.w;
        }
    }

    // ---- softplus(+bias) - shift, write h tile ----
    {
        float4 bb0 = *reinterpret_cast<const float4*>(&b1s[f0]);
        float4 bb1 = *reinterpret_cast<const float4*>(&b1s[f0 + 4]);
        #pragma unroll
        for (int i = 0; i < 8; i++) {
            float4 o0, o1;
            o0.x = softplus_fast(acc[i][0] + bb0.x) - SHIFT_LN2;
            o0.y = softplus_fast(acc[i][1] + bb0.y) - SHIFT_LN2;
            o0.z = softplus_fast(acc[i][2] + bb0.z) - SHIFT_LN2;
            o0.w = softplus_fast(acc[i][3] + bb0.w) - SHIFT_LN2;
            o1.x = softplus_fast(acc[i][4] + bb1.x) - SHIFT_LN2;
            o1.y = softplus_fast(acc[i][5] + bb1.y) - SHIFT_LN2;
            o1.z = softplus_fast(acc[i][6] + bb1.z) - SHIFT_LN2;
            o1.w = softplus_fast(acc[i][7] + bb1.w) - SHIFT_LN2;
            *reinterpret_cast<float4*>(&hs[(er0 + i) * 132 + f0])     = o0;
            *reinterpret_cast<float4*>(&hs[(er0 + i) * 132 + f0 + 4]) = o1;
        }
    }
    __syncthreads();

    // ---- stage 2: acc = h_tile @ w2T  (K = 128) ----
    #pragma unroll
    for (int i = 0; i < 8; i++)
        #pragma unroll
        for (int j = 0; j < 8; j++) acc[i][j] = 0.f;

    #pragma unroll 8
    for (int k = 0; k < 128; k++) {
        float4 b0 = *reinterpret_cast<const float4*>(&w2T[k * 128 + f0]);
        float4 b1 = *reinterpret_cast<const float4*>(&w2T[k * 128 + f0 + 4]);
        #pragma unroll
        for (int i = 0; i < 8; i++) {
            float av = hs[(er0 + i) * 132 + k];
            acc[i][0] += av * b0.x; acc[i][1] += av * b0.y;
            acc[i][2] += av * b0.z; acc[i][3] += av * b0.w;
            acc[i][4] += av * b1.x; acc[i][5] += av * b1.y;
            acc[i][6] += av * b1.z; acc[i][7] += av * b1.w;
        }
    }

    // ---- epilogue: (+b2) * C * vl[j], vectorized store ----
    {
        float4 bb0 = *reinterpret_cast<const float4*>(&b2s[f0]);
        float4 bb1 = *reinterpret_cast<const float4*>(&b2s[f0 + 4]);
        #pragma unroll
        for (int i = 0; i < 8; i++) {
            int el = er0 + i;
            long long e = e0 + el;
            if (e < E) {
                float Cv = Cs[el];
                const float4* vp =
                    reinterpret_cast<const float4*>(&g_vl[(size_t)js[el] * 128 + f0]);
                float4 v0 = vp[0], v1 = vp[1];
                float4 o0, o1;
                o0.x = (acc[i][0] + bb0.x) * Cv * v0.x;
                o0.y = (acc[i][1] + bb0.y) * Cv * v0.y;
                o0.z = (acc[i][2] + bb0.z) * Cv * v0.z;
                o0.w = (acc[i][3] + bb0.w) * Cv * v0.w;
                o1.x = (acc[i][4] + bb1.x) * Cv * v1.x;
                o1.y = (acc[i][5] + bb1.y) * Cv * v1.y;
                o1.z = (acc[i][6] + bb1.z) * Cv * v1.z;
                o1.w = (acc[i][7] + bb1.w) * Cv * v1.w;
                *reinterpret_cast<float4*>(&out[(size_t)e * 128 + f0])     = o0;
                *reinterpret_cast<float4*>(&out[(size_t)e * 128 + f0 + 4]) = o1;
            }
        }
    }
}

// ---------------------------------------------------------------------------
extern "C" void kernel_launch(void* const* d_in, const int* in_sizes, int n_in,
                              void* d_out, int out_size)
{
    const float* v          = (const float*)d_in[0];
    const float* dist       = (const float*)d_in[1];
    const float* dist_emb   = (const float*)d_in[2];
    const int*   edge_index = (const int*)d_in[3];   // int32 [2][E]
    const float* lin_w      = (const float*)d_in[4];
    const float* mlp1_w     = (const float*)d_in[5];
    const float* mlp1_b     = (const float*)d_in[6];
    const float* mlp2_w     = (const float*)d_in[7];
    const float* mlp2_b     = (const float*)d_in[8];
    float*       out        = (float*)d_out;

    const int N = in_sizes[0] / 128;
    const int E = in_sizes[1];

    const size_t smemA = (size_t)(128 * 128 + 128 * 132) * sizeof(float);
    const size_t smemB = (size_t)(50 * 128 + 128 * 128 + 3 * 128 +
                                  128 * 52 + 128 * 132) * sizeof(float)
                         + 128 * sizeof(int);

    cudaFuncSetAttribute(vl_kernel,   cudaFuncAttributeMaxDynamicSharedMemorySize, (int)smemA);
    cudaFuncSetAttribute(edge_kernel, cudaFuncAttributeMaxDynamicSharedMemorySize, (int)smemB);

    vl_kernel<<<(N + 127) / 128, 256, smemA>>>(v, lin_w, N);
    edge_kernel<<<(E + 127) / 128, 256, smemB>>>(dist, dist_emb, edge_index,
                                                 mlp1_w, mlp1_b, mlp2_w, mlp2_b,
                                                 out, E);
}

// round 3
// speedup vs baseline: 1.0065x; 1.0065x over previous
#include <cuda_runtime.h>

// ---------------------------------------------------------------------------
// update_e: SchNet CFConv edge message
//   C    = 0.5*(cos(pi*d/10)+1)
//   h    = softplus(dist_emb @ mlp1_w^T + b1) - log(2)
//   W    = (h @ mlp2_w^T + b2) * C
//   out  = (v @ lin_w^T)[j] * W
//
// R1 fix: edge_index is int32 (JAX x64 disabled downcasts int64 -> int32).
// fp32 FFMA baseline:
//   Kernel A: vl = v @ lin_w^T  -> __device__ scratch (25.6 MB, L2-resident)
//   Kernel B: fused per-edge-tile double GEMM + epilogue.
//     block = 256 threads (16x16), tile = 128 edges x 128 feats,
//     8x8 register micro-tile, weights + tiles in SMEM (~187 KB, 1 CTA/SM).
// ---------------------------------------------------------------------------

#define SHIFT_LN2       0.69314718055994530942f
#define PI_OVER_CUTOFF  0.31415926535897932385f   // pi / 10

__device__ float g_vl[50000 * 128];

extern __shared__ float smem[];

__device__ __forceinline__ float softplus_fast(float x) {
    // log(1+e^x); for x>15 the correction is < 3e-7
    return (x > 15.f) ? x : __logf(1.f + __expf(x));
}

// ------------------------- Kernel A: vl = v @ lin_w^T -----------------------
__global__ void __launch_bounds__(256, 1)
vl_kernel(const float* __restrict__ v, const float* __restrict__ lin_w, int nrows)
{
    float* wT = smem;               // [128][128]  wT[k][f] = lin_w[f][k]
    float* a  = smem + 128 * 128;   // [128][132]  v rows (padded)
    const int tid = threadIdx.x;
    const int r0  = blockIdx.x * 128;

    for (int i = tid; i < 128 * 128; i += 256) {
        int f = i >> 7, k = i & 127;
        wT[k * 128 + f] = lin_w[i];
    }
    for (int i = tid; i < 128 * 128; i += 256) {
        int r = i >> 7, k = i & 127;
        int rg = r0 + r;
        a[r * 132 + k] = (rg < nrows) ? v[(size_t)rg * 128 + k] : 0.f;
    }
    __syncthreads();

    const int tx = tid & 15, ty = tid >> 4;
    const int f0 = tx * 8, rr0 = ty * 8;

    float acc[8][8];
    #pragma unroll
    for (int i = 0; i < 8; i++)
        #pragma unroll
        for (int j = 0; j < 8; j++) acc[i][j] = 0.f;

    #pragma unroll 8
    for (int k = 0; k < 128; k++) {
        float4 b0 = *reinterpret_cast<const float4*>(&wT[k * 128 + f0]);
        float4 b1 = *reinterpret_cast<const float4*>(&wT[k * 128 + f0 + 4]);
        #pragma unroll
        for (int i = 0; i < 8; i++) {
            float av = a[(rr0 + i) * 132 + k];
            acc[i][0] += av * b0.x; acc[i][1] += av * b0.y;
            acc[i][2] += av * b0.z; acc[i][3] += av * b0.w;
            acc[i][4] += av * b1.x; acc[i][5] += av * b1.y;
            acc[i][6] += av * b1.z; acc[i][7] += av * b1.w;
        }
    }

    #pragma unroll
    for (int i = 0; i < 8; i++) {
        int rg = r0 + rr0 + i;
        if (rg < nrows) {
            float4 o0 = make_float4(acc[i][0], acc[i][1], acc[i][2], acc[i][3]);
            float4 o1 = make_float4(acc[i][4], acc[i][5], acc[i][6], acc[i][7]);
            *reinterpret_cast<float4*>(&g_vl[(size_t)rg * 128 + f0])     = o0;
            *reinterpret_cast<float4*>(&g_vl[(size_t)rg * 128 + f0 + 4]) = o1;
        }
    }
}

// --------------------- Kernel B: fused edge tile kernel ---------------------
__global__ void __launch_bounds__(256, 1)
edge_kernel(const float* __restrict__ dist,
            const float* __restrict__ dist_emb,
            const int* __restrict__ edge_index,   // int32! row 0 = source nodes
            const float* __restrict__ mlp1_w, const float* __restrict__ mlp1_b,
            const float* __restrict__ mlp2_w, const float* __restrict__ mlp2_b,
            float* __restrict__ out, int E)
{
    float* w1T = smem;                     // [50][128]   w1T[g][f] = mlp1_w[f][g]
    float* w2T = w1T + 50 * 128;           // [128][128]  w2T[k][f] = mlp2_w[f][k]
    float* b1s = w2T + 128 * 128;          // [128]
    float* b2s = b1s + 128;                // [128]
    float* Cs  = b2s + 128;                // [128] cosine cutoff per edge
    float* emb = Cs + 128;                 // [128][52]   emb tile (padded)
    float* hs  = emb + 128 * 52;           // [128][132]  h tile (padded)
    int*   js  = (int*)(hs + 128 * 132);   // [128] source node per edge

    const int tid = threadIdx.x;
    const long long e0 = (long long)blockIdx.x * 128;

    // ---- stage tile + weights into SMEM ----
    for (int i = tid; i < 50 * 128; i += 256) {
        int f = i / 50, g = i - f * 50;
        w1T[g * 128 + f] = mlp1_w[i];
    }
    for (int i = tid; i < 128 * 128; i += 256) {
        int f = i >> 7, k = i & 127;
        w2T[k * 128 + f] = mlp2_w[i];
    }
    if (tid < 128) {
        b1s[tid] = mlp1_b[tid];
        b2s[tid] = mlp2_b[tid];
        long long e = e0 + tid;
        if (e < E) {
            float d = dist[e];
            Cs[tid] = 0.5f * (__cosf(d * PI_OVER_CUTOFF) + 1.f);
            js[tid] = edge_index[e];        // row 0 (source), int32
        } else {
            Cs[tid] = 0.f;
            js[tid] = 0;
        }
    }
    for (int i = tid; i < 128 * 50; i += 256) {
        int el = i / 50, g = i - el * 50;
        long long e = e0 + el;
        emb[el * 52 + g] = (e < E) ? dist_emb[e * 50 + g] : 0.f;
    }
    __syncthreads();

    const int tx = tid & 15, ty = tid >> 4;
    const int f0 = tx * 8, er0 = ty * 8;

    // ---- stage 1: acc = emb_tile @ w1T  (K = 50) ----
    float acc[8][8];
    #pragma unroll
    for (int i = 0; i < 8; i++)
        #pragma unroll
        for (int j = 0; j < 8; j++) acc[i][j] = 0.f;

    #pragma unroll 5
    for (int g = 0; g < 50; g++) {
        float4 b0 = *reinterpret_cast<const float4*>(&w1T[g * 128 + f0]);
        float4 b1 = *reinterpret_cast<const float4*>(&w1T[g * 128 + f0 + 4]);
        #pragma unroll
        for (int i = 0; i < 8; i++) {
            float av = emb[(er0 + i) * 52 + g];
            acc[i][0] += av * b0.x; acc[i][1] += av * b0.y;
            acc[i][2] += av * b0.z; acc[i][3] += av * b0.w;
            acc[i][4] += av * b1.x; acc[i][5] += av * b1.y;
            acc[i][6] += av * b1.z; acc[i][7] += av * b1.w;
        }
    }

    // ---- softplus(+bias) - shift, write h tile ----
    {
        float4 bb0 = *reinterpret_cast<const float4*>(&b1s[f0]);
        float4 bb1 = *reinterpret_cast<const float4*>(&b1s[f0 + 4]);
        #pragma unroll
        for (int i = 0; i < 8; i++) {
            float4 o0, o1;
            o0.x = softplus_fast(acc[i][0] + bb0.x) - SHIFT_LN2;
            o0.y = softplus_fast(acc[i][1] + bb0.y) - SHIFT_LN2;
            o0.z = softplus_fast(acc[i][2] + bb0.z) - SHIFT_LN2;
            o0.w = softplus_fast(acc[i][3] + bb0.w) - SHIFT_LN2;
            o1.x = softplus_fast(acc[i][4] + bb1.x) - SHIFT_LN2;
            o1.y = softplus_fast(acc[i][5] + bb1.y) - SHIFT_LN2;
            o1.z = softplus_fast(acc[i][6] + bb1.z) - SHIFT_LN2;
            o1.w = softplus_fast(acc[i][7] + bb1.w) - SHIFT_LN2;
            *reinterpret_cast<float4*>(&hs[(er0 + i) * 132 + f0])     = o0;
            *reinterpret_cast<float4*>(&hs[(er0 + i) * 132 + f0 + 4]) = o1;
        }
    }
    __syncthreads();

    // ---- stage 2: acc = h_tile @ w2T  (K = 128) ----
    #pragma unroll
    for (int i = 0; i < 8; i++)
        #pragma unroll
        for (int j = 0; j < 8; j++) acc[i][j] = 0.f;

    #pragma unroll 8
    for (int k = 0; k < 128; k++) {
        float4 b0 = *reinterpret_cast<const float4*>(&w2T[k * 128 + f0]);
        float4 b1 = *reinterpret_cast<const float4*>(&w2T[k * 128 + f0 + 4]);
        #pragma unroll
        for (int i = 0; i < 8; i++) {
            float av = hs[(er0 + i) * 132 + k];
            acc[i][0] += av * b0.x; acc[i][1] += av * b0.y;
            acc[i][2] += av * b0.z; acc[i][3] += av * b0.w;
            acc[i][4] += av * b1.x; acc[i][5] += av * b1.y;
            acc[i][6] += av * b1.z; acc[i][7] += av * b1.w;
        }
    }

    // ---- epilogue: (+b2) * C * vl[j], vectorized store ----
    {
        float4 bb0 = *reinterpret_cast<const float4*>(&b2s[f0]);
        float4 bb1 = *reinterpret_cast<const float4*>(&b2s[f0 + 4]);
        #pragma unroll
        for (int i = 0; i < 8; i++) {
            int el = er0 + i;
            long long e = e0 + el;
            if (e < E) {
                float Cv = Cs[el];
                const float4* vp =
                    reinterpret_cast<const float4*>(&g_vl[(size_t)js[el] * 128 + f0]);
                float4 v0 = vp[0], v1 = vp[1];
                float4 o0, o1;
                o0.x = (acc[i][0] + bb0.x) * Cv * v0.x;
                o0.y = (acc[i][1] + bb0.y) * Cv * v0.y;
                o0.z = (acc[i][2] + bb0.z) * Cv * v0.z;
                o0.w = (acc[i][3] + bb0.w) * Cv * v0.w;
                o1.x = (acc[i][4] + bb1.x) * Cv * v1.x;
                o1.y = (acc[i][5] + bb1.y) * Cv * v1.y;
                o1.z = (acc[i][6] + bb1.z) * Cv * v1.z;
                o1.w = (acc[i][7] + bb1.w) * Cv * v1.w;
                *reinterpret_cast<float4*>(&out[(size_t)e * 128 + f0])     = o0;
                *reinterpret_cast<float4*>(&out[(size_t)e * 128 + f0 + 4]) = o1;
            }
        }
    }
}

// ---------------------------------------------------------------------------
extern "C" void kernel_launch(void* const* d_in, const int* in_sizes, int n_in,
                              void* d_out, int out_size)
{
    const float* v          = (const float*)d_in[0];
    const float* dist       = (const float*)d_in[1];
    const float* dist_emb   = (const float*)d_in[2];
    const int*   edge_index = (const int*)d_in[3];   // int32 [2][E]
    const float* lin_w      = (const float*)d_in[4];
    const float* mlp1_w     = (const float*)d_in[5];
    const float* mlp1_b     = (const float*)d_in[6];
    const float* mlp2_w     = (const float*)d_in[7];
    const float* mlp2_b     = (const float*)d_in[8];
    float*       out        = (float*)d_out;

    const int N = in_sizes[0] / 128;
    const int E = in_sizes[1];

    const size_t smemA = (size_t)(128 * 128 + 128 * 132) * sizeof(float);
    const size_t smemB = (size_t)(50 * 128 + 128 * 128 + 3 * 128 +
                                  128 * 52 + 128 * 132) * sizeof(float)
                         + 128 * sizeof(int);

    cudaFuncSetAttribute(vl_kernel,   cudaFuncAttributeMaxDynamicSharedMemorySize, (int)smemA);
    cudaFuncSetAttribute(edge_kernel, cudaFuncAttributeMaxDynamicSharedMemorySize, (int)smemB);

    vl_kernel<<<(N + 127) / 128, 256, smemA>>>(v, lin_w, N);
    edge_kernel<<<(E + 127) / 128, 256, smemB>>>(dist, dist_emb, edge_index,
                                                 mlp1_w, mlp1_b, mlp2_w, mlp2_b,
                                                 out, E);
}

// round 7
// speedup vs baseline: 2.2752x; 2.2604x over previous
#include <cuda_runtime.h>
#include <cuda_bf16.h>
#include <cstdint>

// ---------------------------------------------------------------------------
// update_e: SchNet CFConv edge message — mma.sync bf16 split-compensated.
//   C    = 0.5*(cos(pi*d/10)+1)
//   h    = softplus(dist_emb @ mlp1_w^T + b1) - log(2)
//   W    = (h @ mlp2_w^T + b2) * C
//   out  = (v @ lin_w^T)[j] * W
//
// tcgen05 is unavailable (harness emits compute_103 PTX, not compute_103a),
// so both edge GEMMs run on mma.sync.m16n8k16 bf16 (portable HMMA path) with
// 2-way bf16 hi/lo split compensation (3 MMAs/GEMM -> ~2^-18 product error).
//
// edge kernel: persistent, grid=152, 512 thr (16 warps in 4x4), tile = 128
// edges x 128 feats. Weights split once into SMEM. Row strides 72/136 bf16
// (= 36/68 words, both ≡ 4 mod 32) -> conflict-free fragment LDS.
// ---------------------------------------------------------------------------

#define SHIFT_LN2       0.69314718055994530942f
#define PI_OVER_CUTOFF  0.31415926535897932385f

__device__ float g_vl[50000 * 128];

extern __shared__ uint32_t smw[];

// ---- SMEM word-offsets (edge kernel) ----
static constexpr int ST1 = 36;     // stride (words) for K=64 regions (72 bf16)
static constexpr int ST2 = 68;     // stride (words) for K=128 regions (136 bf16)
static constexpr int W1HI = 0;                       // [128][36]
static constexpr int W1LO = W1HI + 128 * ST1;        // 4608
static constexpr int W2HI = W1LO + 128 * ST1;        // [128][68]
static constexpr int W2LO = W2HI + 128 * ST2;
static constexpr int EMBHI = W2LO + 128 * ST2;       // [128][36]
static constexpr int EMBLO = EMBHI + 128 * ST1;
static constexpr int HHI = EMBLO + 128 * ST1;        // [128][68]
static constexpr int HLO = HHI + 128 * ST2;
static constexpr int B1W = HLO + 128 * ST2;          // 128 f32
static constexpr int B2W = B1W + 128;
static constexpr int CSW = B2W + 128;                // 128 f32
static constexpr int JSW = CSW + 128;                // 128 i32
static constexpr int SMEM_WORDS = JSW + 128;         // 53760 words = 215040 B

// ---------------------------- helpers --------------------------------------
__device__ __forceinline__ float softplus_fast(float x) {
    return (x > 15.f) ? x : __logf(1.f + __expf(x));
}
__device__ __forceinline__ uint32_t pack_bf(__nv_bfloat16 a, __nv_bfloat16 b) {
    return (uint32_t)__bfloat16_as_ushort(a) | ((uint32_t)__bfloat16_as_ushort(b) << 16);
}
// split two floats into packed bf16 hi word + lo (residual) word; lo16 = elem0
__device__ __forceinline__ void split2(float x0, float x1, uint32_t& hi, uint32_t& lo) {
    __nv_bfloat16 h0 = __float2bfloat16(x0);
    __nv_bfloat16 h1 = __float2bfloat16(x1);
    __nv_bfloat16 l0 = __float2bfloat16(x0 - __bfloat162float(h0));
    __nv_bfloat16 l1 = __float2bfloat16(x1 - __bfloat162float(h1));
    hi = pack_bf(h0, h1);
    lo = pack_bf(l0, l1);
}

__device__ __forceinline__ void mma16816(float d[4], const uint32_t a[4], const uint32_t b[2]) {
    asm volatile(
        "mma.sync.aligned.m16n8k16.row.col.f32.bf16.bf16.f32 "
        "{%0,%1,%2,%3}, {%4,%5,%6,%7}, {%8,%9}, {%0,%1,%2,%3};"
        : "+f"(d[0]), "+f"(d[1]), "+f"(d[2]), "+f"(d[3])
        : "r"(a[0]), "r"(a[1]), "r"(a[2]), "r"(a[3]), "r"(b[0]), "r"(b[1]));
}

// ------------------------- Kernel A: vl = v @ lin_w^T -----------------------
__global__ void __launch_bounds__(256, 1)
vl_kernel(const float* __restrict__ v, const float* __restrict__ lin_w, int nrows)
{
    float* smem = (float*)smw;
    float* wT = smem;               // [128][128]
    float* a  = smem + 128 * 128;   // [128][132]
    const int tid = threadIdx.x;
    const int r0  = blockIdx.x * 128;

    for (int i = tid; i < 128 * 128; i += 256) {
        int f = i >> 7, k = i & 127;
        wT[k * 128 + f] = lin_w[i];
    }
    for (int i = tid; i < 128 * 128; i += 256) {
        int r = i >> 7, k = i & 127;
        int rg = r0 + r;
        a[r * 132 + k] = (rg < nrows) ? v[(size_t)rg * 128 + k] : 0.f;
    }
    __syncthreads();

    const int tx = tid & 15, ty = tid >> 4;
    const int f0 = tx * 8, rr0 = ty * 8;

    float acc[8][8];
    #pragma unroll
    for (int i = 0; i < 8; i++)
        #pragma unroll
        for (int j = 0; j < 8; j++) acc[i][j] = 0.f;

    #pragma unroll 8
    for (int k = 0; k < 128; k++) {
        float4 b0 = *reinterpret_cast<const float4*>(&wT[k * 128 + f0]);
        float4 b1 = *reinterpret_cast<const float4*>(&wT[k * 128 + f0 + 4]);
        #pragma unroll
        for (int i = 0; i < 8; i++) {
            float av = a[(rr0 + i) * 132 + k];
            acc[i][0] += av * b0.x; acc[i][1] += av * b0.y;
            acc[i][2] += av * b0.z; acc[i][3] += av * b0.w;
            acc[i][4] += av * b1.x; acc[i][5] += av * b1.y;
            acc[i][6] += av * b1.z; acc[i][7] += av * b1.w;
        }
    }

    #pragma unroll
    for (int i = 0; i < 8; i++) {
        int rg = r0 + rr0 + i;
        if (rg < nrows) {
            *reinterpret_cast<float4*>(&g_vl[(size_t)rg * 128 + f0]) =
                make_float4(acc[i][0], acc[i][1], acc[i][2], acc[i][3]);
            *reinterpret_cast<float4*>(&g_vl[(size_t)rg * 128 + f0 + 4]) =
                make_float4(acc[i][4], acc[i][5], acc[i][6], acc[i][7]);
        }
    }
}

// ---------------- Kernel B: persistent mma.sync edge kernel -----------------
__global__ void __launch_bounds__(512, 1)
edge_mma_kernel(const float* __restrict__ dist,
                const float* __restrict__ dist_emb,
                const int* __restrict__ edge_index,   // int32, row 0 = source
                const float* __restrict__ mlp1_w, const float* __restrict__ mlp1_b,
                const float* __restrict__ mlp2_w, const float* __restrict__ mlp2_b,
                float* __restrict__ out, int E, int ntiles)
{
    const int tid  = threadIdx.x;
    const int lane = tid & 31;
    const int wid  = tid >> 5;
    const int g    = lane >> 2;      // group id 0..7
    const int t    = lane & 3;       // thread-in-group 0..3
    const int wm   = wid & 3;        // warp m index (edges)
    const int wn   = wid >> 2;       // warp n index (feats)
    const int m0   = wm * 32;
    const int n0   = wn * 32;

    float* b1f = (float*)(smw + B1W);
    float* b2f = (float*)(smw + B2W);
    float* Csf = (float*)(smw + CSW);
    int*   Jsi = (int*)(smw + JSW);

    // ---- zero padded regions (w1 K 50..63, emb K 50..63) once ----
    for (int i = tid; i < 128 * ST1; i += 512) {
        smw[W1HI + i] = 0; smw[W1LO + i] = 0;
        smw[EMBHI + i] = 0; smw[EMBLO + i] = 0;
    }
    __syncthreads();

    // ---- stage weights as bf16 hi/lo (once per CTA) ----
    for (int i = tid; i < 128 * 25; i += 512) {           // w1: 128 x 50
        int f = i / 25, c = i - f * 25;
        float2 w = *(const float2*)(mlp1_w + (size_t)f * 50 + 2 * c);
        uint32_t hi, lo; split2(w.x, w.y, hi, lo);
        smw[W1HI + f * ST1 + c] = hi;
        smw[W1LO + f * ST1 + c] = lo;
    }
    for (int i = tid; i < 128 * 64; i += 512) {           // w2: 128 x 128
        int f = i >> 6, c = i & 63;
        float2 w = *(const float2*)(mlp2_w + (size_t)f * 128 + 2 * c);
        uint32_t hi, lo; split2(w.x, w.y, hi, lo);
        smw[W2HI + f * ST2 + c] = hi;
        smw[W2LO + f * ST2 + c] = lo;
    }
    if (tid < 128) { b1f[tid] = mlp1_b[tid]; b2f[tid] = mlp2_b[tid]; }

    for (int tile = blockIdx.x; tile < ntiles; tile += gridDim.x) {
        __syncthreads();   // protects CS/JS/EMB against prior-tile readers

        // ---- per-edge scalars ----
        if (tid < 128) {
            int e = tile * 128 + tid;
            if (e < E) {
                Csf[tid] = 0.5f * (__cosf(dist[e] * PI_OVER_CUTOFF) + 1.f);
                Jsi[tid] = edge_index[e];
            } else { Csf[tid] = 0.f; Jsi[tid] = 0; }
        }
        // ---- emb tile -> bf16 hi/lo ----
        for (int i = tid; i < 128 * 25; i += 512) {
            int row = i / 25, c = i - row * 25;
            int e = tile * 128 + row;
            float2 w = (e < E) ? *(const float2*)(dist_emb + (size_t)e * 50 + 2 * c)
                               : make_float2(0.f, 0.f);
            uint32_t hi, lo; split2(w.x, w.y, hi, lo);
            smw[EMBHI + row * ST1 + c] = hi;
            smw[EMBLO + row * ST1 + c] = lo;
        }
        __syncthreads();

        // ================= GEMM1: h = emb @ w1^T (K=64) =================
        float acc[2][4][4];
        #pragma unroll
        for (int mt = 0; mt < 2; mt++)
            #pragma unroll
            for (int nt = 0; nt < 4; nt++)
                #pragma unroll
                for (int q = 0; q < 4; q++) acc[mt][nt][q] = 0.f;

        #pragma unroll
        for (int ks = 0; ks < 4; ks++) {
            const int kw = ks * 8;
            uint32_t ahi[2][4], alo[2][4];
            #pragma unroll
            for (int mt = 0; mt < 2; mt++) {
                int r = (m0 + mt * 16 + g) * ST1 + kw + t;
                ahi[mt][0] = smw[EMBHI + r];
                ahi[mt][1] = smw[EMBHI + r + 8 * ST1];
                ahi[mt][2] = smw[EMBHI + r + 4];
                ahi[mt][3] = smw[EMBHI + r + 8 * ST1 + 4];
                alo[mt][0] = smw[EMBLO + r];
                alo[mt][1] = smw[EMBLO + r + 8 * ST1];
                alo[mt][2] = smw[EMBLO + r + 4];
                alo[mt][3] = smw[EMBLO + r + 8 * ST1 + 4];
            }
            uint32_t bhi[4][2], blo[4][2];
            #pragma unroll
            for (int nt = 0; nt < 4; nt++) {
                int rb = (n0 + nt * 8 + g) * ST1 + kw + t;
                bhi[nt][0] = smw[W1HI + rb]; bhi[nt][1] = smw[W1HI + rb + 4];
                blo[nt][0] = smw[W1LO + rb]; blo[nt][1] = smw[W1LO + rb + 4];
            }
            #pragma unroll
            for (int mt = 0; mt < 2; mt++)
                #pragma unroll
                for (int nt = 0; nt < 4; nt++) {
                    mma16816(acc[mt][nt], ahi[mt], bhi[nt]);
                    mma16816(acc[mt][nt], ahi[mt], blo[nt]);
                    mma16816(acc[mt][nt], alo[mt], bhi[nt]);
                }
        }

        // ---- softplus(+b1) - ln2 -> split -> h SMEM ----
        #pragma unroll
        for (int mt = 0; mt < 2; mt++) {
            int row0 = m0 + mt * 16 + g;
            #pragma unroll
            for (int nt = 0; nt < 4; nt++) {
                int f = n0 + nt * 8 + 2 * t;
                float bb0 = b1f[f], bb1 = b1f[f + 1];
                int col = (n0 >> 1) + nt * 4 + t;
                uint32_t hi, lo;
                split2(softplus_fast(acc[mt][nt][0] + bb0) - SHIFT_LN2,
                       softplus_fast(acc[mt][nt][1] + bb1) - SHIFT_LN2, hi, lo);
                smw[HHI + row0 * ST2 + col] = hi;
                smw[HLO + row0 * ST2 + col] = lo;
                split2(softplus_fast(acc[mt][nt][2] + bb0) - SHIFT_LN2,
                       softplus_fast(acc[mt][nt][3] + bb1) - SHIFT_LN2, hi, lo);
                smw[HHI + (row0 + 8) * ST2 + col] = hi;
                smw[HLO + (row0 + 8) * ST2 + col] = lo;
            }
        }
        __syncthreads();

        // ================= GEMM2: W = h @ w2^T (K=128) =================
        #pragma unroll
        for (int mt = 0; mt < 2; mt++)
            #pragma unroll
            for (int nt = 0; nt < 4; nt++)
                #pragma unroll
                for (int q = 0; q < 4; q++) acc[mt][nt][q] = 0.f;

        #pragma unroll
        for (int ks = 0; ks < 8; ks++) {
            const int kw = ks * 8;
            uint32_t ahi[2][4], alo[2][4];
            #pragma unroll
            for (int mt = 0; mt < 2; mt++) {
                int r = (m0 + mt * 16 + g) * ST2 + kw + t;
                ahi[mt][0] = smw[HHI + r];
                ahi[mt][1] = smw[HHI + r + 8 * ST2];
                ahi[mt][2] = smw[HHI + r + 4];
                ahi[mt][3] = smw[HHI + r + 8 * ST2 + 4];
                alo[mt][0] = smw[HLO + r];
                alo[mt][1] = smw[HLO + r + 8 * ST2];
                alo[mt][2] = smw[HLO + r + 4];
                alo[mt][3] = smw[HLO + r + 8 * ST2 + 4];
            }
            uint32_t bhi[4][2], blo[4][2];
            #pragma unroll
            for (int nt = 0; nt < 4; nt++) {
                int rb = (n0 + nt * 8 + g) * ST2 + kw + t;
                bhi[nt][0] = smw[W2HI + rb]; bhi[nt][1] = smw[W2HI + rb + 4];
                blo[nt][0] = smw[W2LO + rb]; blo[nt][1] = smw[W2LO + rb + 4];
            }
            #pragma unroll
            for (int mt = 0; mt < 2; mt++)
                #pragma unroll
                for (int nt = 0; nt < 4; nt++) {
                    mma16816(acc[mt][nt], ahi[mt], bhi[nt]);
                    mma16816(acc[mt][nt], ahi[mt], blo[nt]);
                    mma16816(acc[mt][nt], alo[mt], bhi[nt]);
                }
        }

        // ---- epilogue: (acc + b2)*C*vl[j] -> out ----
        #pragma unroll
        for (int mt = 0; mt < 2; mt++) {
            int el0 = m0 + mt * 16 + g;        // local edge rows el0, el0+8
            int e0 = tile * 128 + el0;
            int e1 = e0 + 8;
            #pragma unroll
            for (int nt = 0; nt < 4; nt++) {
                int f = n0 + nt * 8 + 2 * t;
                float2 bb = *(const float2*)(b2f + f);
                if (e0 < E) {
                    float Cv = Csf[el0];
                    const float2 vv = *(const float2*)(g_vl + (size_t)Jsi[el0] * 128 + f);
                    float2 o;
                    o.x = (acc[mt][nt][0] + bb.x) * Cv * vv.x;
                    o.y = (acc[mt][nt][1] + bb.y) * Cv * vv.y;
                    *(float2*)(out + (size_t)e0 * 128 + f) = o;
                }
                if (e1 < E) {
                    float Cv = Csf[el0 + 8];
                    const float2 vv = *(const float2*)(g_vl + (size_t)Jsi[el0 + 8] * 128 + f);
                    float2 o;
                    o.x = (acc[mt][nt][2] + bb.x) * Cv * vv.x;
                    o.y = (acc[mt][nt][3] + bb.y) * Cv * vv.y;
                    *(float2*)(out + (size_t)e1 * 128 + f) = o;
                }
            }
        }
    }
}

// ---------------------------------------------------------------------------
extern "C" void kernel_launch(void* const* d_in, const int* in_sizes, int n_in,
                              void* d_out, int out_size)
{
    const float* v          = (const float*)d_in[0];
    const float* dist       = (const float*)d_in[1];
    const float* dist_emb   = (const float*)d_in[2];
    const int*   edge_index = (const int*)d_in[3];   // int32 [2][E]
    const float* lin_w      = (const float*)d_in[4];
    const float* mlp1_w     = (const float*)d_in[5];
    const float* mlp1_b     = (const float*)d_in[6];
    const float* mlp2_w     = (const float*)d_in[7];
    const float* mlp2_b     = (const float*)d_in[8];
    float*       out        = (float*)d_out;

    const int N = in_sizes[0] / 128;
    const int E = in_sizes[1];
    const int ntiles = (E + 127) / 128;

    const size_t smemA = (size_t)(128 * 128 + 128 * 132) * sizeof(float);
    const size_t smemB = (size_t)SMEM_WORDS * 4;

    cudaFuncSetAttribute(vl_kernel, cudaFuncAttributeMaxDynamicSharedMemorySize, (int)smemA);
    cudaFuncSetAttribute(edge_mma_kernel, cudaFuncAttributeMaxDynamicSharedMemorySize, (int)smemB);

    vl_kernel<<<(N + 127) / 128, 256, smemA>>>(v, lin_w, N);

    int grid = 152;
    if (grid > ntiles) grid = ntiles;
    edge_mma_kernel<<<grid, 512, smemB>>>(dist, dist_emb, edge_index,
                                          mlp1_w, mlp1_b, mlp2_w, mlp2_b,
                                          out, E, ntiles);
}

// round 9
// speedup vs baseline: 2.9086x; 1.2784x over previous
#include <cuda_runtime.h>
#include <cuda_fp16.h>
#include <cstdint>

// ---------------------------------------------------------------------------
// update_e: SchNet CFConv edge message — mma.sync fp16, A-split compensation.
//   C    = 0.5*(cos(pi*d/10)+1)
//   h    = softplus(dist_emb @ mlp1_w^T + b1) - log(2)
//   W    = (h @ mlp2_w^T + b2) * C
//   out  = (v @ lin_w^T)[j] * W
//
// R8: fp16 (11-bit mantissa) instead of bf16. A = Ahi + Alo (fp16 split),
// B = single fp16 -> 2 MMAs per GEMM, residual error ~2^-11 RMS ≈ 3e-4.
// SMEM halves (108KB/CTA) -> 2 CTAs/SM -> phases overlap across CTAs.
// edge kernel: persistent, grid=304, 256 thr (8 warps, 2x4), tile = 64 edges.
// ---------------------------------------------------------------------------

#define SHIFT_LN2       0.69314718055994530942f
#define PI_OVER_CUTOFF  0.31415926535897932385f

__device__ float g_vl[50000 * 128];

extern __shared__ uint32_t smw[];

// ---- SMEM word-offsets (edge kernel) ----
static constexpr int ST1 = 36;     // words per row, K=64 fp16 (32 words) + 4 pad
static constexpr int ST2 = 68;     // words per row, K=128 fp16 (64 words) + 4 pad
static constexpr int W1S   = 0;                      // [128][36] fp16x2
static constexpr int W2S   = W1S + 128 * ST1;        // [128][68]
static constexpr int EMBHI = W2S + 128 * ST2;        // [64][36]
static constexpr int EMBLO = EMBHI + 64 * ST1;
static constexpr int HHI   = EMBLO + 64 * ST1;       // [64][68]
static constexpr int HLO   = HHI + 64 * ST2;
static constexpr int B1W   = HLO + 64 * ST2;         // 128 f32
static constexpr int B2W   = B1W + 128;
static constexpr int CSW   = B2W + 128;              // 64 f32
static constexpr int JSW   = CSW + 64;               // 64 i32
static constexpr int SMEM_WORDS = JSW + 64;          // 27008 words = 108032 B

// ---------------------------- helpers --------------------------------------
__device__ __forceinline__ float softplus_fast(float x) {
    return (x > 15.f) ? x : __logf(1.f + __expf(x));
}
__device__ __forceinline__ uint32_t pack_h2(__half a, __half b) {
    __half2 p = __halves2half2(a, b);
    return *reinterpret_cast<uint32_t*>(&p);
}
// single fp16 pack of two floats
__device__ __forceinline__ uint32_t cvt2(float x0, float x1) {
    return pack_h2(__float2half(x0), __float2half(x1));
}
// split two floats into fp16 hi word + residual lo word
__device__ __forceinline__ void split2(float x0, float x1, uint32_t& hi, uint32_t& lo) {
    __half h0 = __float2half(x0);
    __half h1 = __float2half(x1);
    __half l0 = __float2half(x0 - __half2float(h0));
    __half l1 = __float2half(x1 - __half2float(h1));
    hi = pack_h2(h0, h1);
    lo = pack_h2(l0, l1);
}

__device__ __forceinline__ void mma16816(float d[4], const uint32_t a[4], const uint32_t b[2]) {
    asm volatile(
        "mma.sync.aligned.m16n8k16.row.col.f32.f16.f16.f32 "
        "{%0,%1,%2,%3}, {%4,%5,%6,%7}, {%8,%9}, {%0,%1,%2,%3};"
        : "+f"(d[0]), "+f"(d[1]), "+f"(d[2]), "+f"(d[3])
        : "r"(a[0]), "r"(a[1]), "r"(a[2]), "r"(a[3]), "r"(b[0]), "r"(b[1]));
}

// ------------------------- Kernel A: vl = v @ lin_w^T -----------------------
__global__ void __launch_bounds__(256, 1)
vl_kernel(const float* __restrict__ v, const float* __restrict__ lin_w, int nrows)
{
    float* smem = (float*)smw;
    float* wT = smem;               // [128][128]
    float* a  = smem + 128 * 128;   // [128][132]
    const int tid = threadIdx.x;
    const int r0  = blockIdx.x * 128;

    for (int i = tid; i < 128 * 128; i += 256) {
        int f = i >> 7, k = i & 127;
        wT[k * 128 + f] = lin_w[i];
    }
    for (int i = tid; i < 128 * 128; i += 256) {
        int r = i >> 7, k = i & 127;
        int rg = r0 + r;
        a[r * 132 + k] = (rg < nrows) ? v[(size_t)rg * 128 + k] : 0.f;
    }
    __syncthreads();

    const int tx = tid & 15, ty = tid >> 4;
    const int f0 = tx * 8, rr0 = ty * 8;

    float acc[8][8];
    #pragma unroll
    for (int i = 0; i < 8; i++)
        #pragma unroll
        for (int j = 0; j < 8; j++) acc[i][j] = 0.f;

    #pragma unroll 8
    for (int k = 0; k < 128; k++) {
        float4 b0 = *reinterpret_cast<const float4*>(&wT[k * 128 + f0]);
        float4 b1 = *reinterpret_cast<const float4*>(&wT[k * 128 + f0 + 4]);
        #pragma unroll
        for (int i = 0; i < 8; i++) {
            float av = a[(rr0 + i) * 132 + k];
            acc[i][0] += av * b0.x; acc[i][1] += av * b0.y;
            acc[i][2] += av * b0.z; acc[i][3] += av * b0.w;
            acc[i][4] += av * b1.x; acc[i][5] += av * b1.y;
            acc[i][6] += av * b1.z; acc[i][7] += av * b1.w;
        }
    }

    #pragma unroll
    for (int i = 0; i < 8; i++) {
        int rg = r0 + rr0 + i;
        if (rg < nrows) {
            *reinterpret_cast<float4*>(&g_vl[(size_t)rg * 128 + f0]) =
                make_float4(acc[i][0], acc[i][1], acc[i][2], acc[i][3]);
            *reinterpret_cast<float4*>(&g_vl[(size_t)rg * 128 + f0 + 4]) =
                make_float4(acc[i][4], acc[i][5], acc[i][6], acc[i][7]);
        }
    }
}

// ---------------- Kernel B: persistent mma.sync edge kernel -----------------
__global__ void __launch_bounds__(256, 2)
edge_mma_kernel(const float* __restrict__ dist,
                const float* __restrict__ dist_emb,
                const int* __restrict__ edge_index,   // int32, row 0 = source
                const float* __restrict__ mlp1_w, const float* __restrict__ mlp1_b,
                const float* __restrict__ mlp2_w, const float* __restrict__ mlp2_b,
                float* __restrict__ out, int E, int ntiles)
{
    const int tid  = threadIdx.x;
    const int lane = tid & 31;
    const int wid  = tid >> 5;
    const int g    = lane >> 2;      // group row 0..7
    const int t    = lane & 3;       // thread-in-group 0..3
    const int wm   = wid & 1;        // warp m index (edges: 2)
    const int wn   = wid >> 1;       // warp n index (feats: 4)
    const int m0   = wm * 32;
    const int n0   = wn * 32;

    float* b1f = (float*)(smw + B1W);
    float* b2f = (float*)(smw + B2W);
    float* Csf = (float*)(smw + CSW);
    int*   Jsi = (int*)(smw + JSW);

    // ---- zero padded K-regions once (w1 cols 50..63 must be 0) ----
    for (int i = tid; i < 128 * ST1; i += 256) smw[W1S + i] = 0;
    for (int i = tid; i < 64 * ST1; i += 256) { smw[EMBHI + i] = 0; smw[EMBLO + i] = 0; }
    __syncthreads();

    // ---- stage weights as fp16 (once per CTA) ----
    for (int i = tid; i < 128 * 25; i += 256) {          // w1: 128 x 50
        int f = i / 25, c = i - f * 25;
        float2 w = *(const float2*)(mlp1_w + (size_t)f * 50 + 2 * c);
        smw[W1S + f * ST1 + c] = cvt2(w.x, w.y);
    }
    for (int i = tid; i < 128 * 64; i += 256) {          // w2: 128 x 128
        int f = i >> 6, c = i & 63;
        float2 w = *(const float2*)(mlp2_w + (size_t)f * 128 + 2 * c);
        smw[W2S + f * ST2 + c] = cvt2(w.x, w.y);
    }
    if (tid < 128) { b1f[tid] = mlp1_b[tid]; b2f[tid] = mlp2_b[tid]; }

    for (int tile = blockIdx.x; tile < ntiles; tile += gridDim.x) {
        __syncthreads();   // protect CS/JS/EMB/H against prior-tile readers

        // ---- per-edge scalars (64 edges) ----
        if (tid < 64) {
            int e = tile * 64 + tid;
            if (e < E) {
                Csf[tid] = 0.5f * (__cosf(dist[e] * PI_OVER_CUTOFF) + 1.f);
                Jsi[tid] = edge_index[e];
            } else { Csf[tid] = 0.f; Jsi[tid] = 0; }
        }
        // ---- emb tile -> fp16 hi/lo ----
        for (int i = tid; i < 64 * 25; i += 256) {
            int row = i / 25, c = i - row * 25;
            int e = tile * 64 + row;
            float2 w = (e < E) ? *(const float2*)(dist_emb + (size_t)e * 50 + 2 * c)
                               : make_float2(0.f, 0.f);
            uint32_t hi, lo; split2(w.x, w.y, hi, lo);
            smw[EMBHI + row * ST1 + c] = hi;
            smw[EMBLO + row * ST1 + c] = lo;
        }
        __syncthreads();

        // ================= GEMM1: h = emb @ w1^T (K=64) =================
        float acc[2][4][4];
        #pragma unroll
        for (int mt = 0; mt < 2; mt++)
            #pragma unroll
            for (int nt = 0; nt < 4; nt++)
                #pragma unroll
                for (int q = 0; q < 4; q++) acc[mt][nt][q] = 0.f;

        #pragma unroll
        for (int ks = 0; ks < 4; ks++) {
            const int kw = ks * 8;
            uint32_t ahi[2][4], alo[2][4];
            #pragma unroll
            for (int mt = 0; mt < 2; mt++) {
                int r = (m0 + mt * 16 + g) * ST1 + kw + t;
                ahi[mt][0] = smw[EMBHI + r];
                ahi[mt][1] = smw[EMBHI + r + 8 * ST1];
                ahi[mt][2] = smw[EMBHI + r + 4];
                ahi[mt][3] = smw[EMBHI + r + 8 * ST1 + 4];
                alo[mt][0] = smw[EMBLO + r];
                alo[mt][1] = smw[EMBLO + r + 8 * ST1];
                alo[mt][2] = smw[EMBLO + r + 4];
                alo[mt][3] = smw[EMBLO + r + 8 * ST1 + 4];
            }
            uint32_t bf[4][2];
            #pragma unroll
            for (int nt = 0; nt < 4; nt++) {
                int rb = (n0 + nt * 8 + g) * ST1 + kw + t;
                bf[nt][0] = smw[W1S + rb]; bf[nt][1] = smw[W1S + rb + 4];
            }
            #pragma unroll
            for (int mt = 0; mt < 2; mt++)
                #pragma unroll
                for (int nt = 0; nt < 4; nt++) {
                    mma16816(acc[mt][nt], ahi[mt], bf[nt]);
                    mma16816(acc[mt][nt], alo[mt], bf[nt]);
                }
        }

        // ---- softplus(+b1) - ln2 -> fp16 split -> h SMEM ----
        #pragma unroll
        for (int mt = 0; mt < 2; mt++) {
            int row0 = m0 + mt * 16 + g;
            #pragma unroll
            for (int nt = 0; nt < 4; nt++) {
                int f = n0 + nt * 8 + 2 * t;
                float bb0 = b1f[f], bb1 = b1f[f + 1];
                int col = (n0 >> 1) + nt * 4 + t;
                uint32_t hi, lo;
                split2(softplus_fast(acc[mt][nt][0] + bb0) - SHIFT_LN2,
                       softplus_fast(acc[mt][nt][1] + bb1) - SHIFT_LN2, hi, lo);
                smw[HHI + row0 * ST2 + col] = hi;
                smw[HLO + row0 * ST2 + col] = lo;
                split2(softplus_fast(acc[mt][nt][2] + bb0) - SHIFT_LN2,
                       softplus_fast(acc[mt][nt][3] + bb1) - SHIFT_LN2, hi, lo);
                smw[HHI + (row0 + 8) * ST2 + col] = hi;
                smw[HLO + (row0 + 8) * ST2 + col] = lo;
            }
        }
        __syncthreads();

        // ================= GEMM2: W = h @ w2^T (K=128) =================
        #pragma unroll
        for (int mt = 0; mt < 2; mt++)
            #pragma unroll
            for (int nt = 0; nt < 4; nt++)
                #pragma unroll
                for (int q = 0; q < 4; q++) acc[mt][nt][q] = 0.f;

        #pragma unroll
        for (int ks = 0; ks < 8; ks++) {
            const int kw = ks * 8;
            uint32_t ahi[2][4], alo[2][4];
            #pragma unroll
            for (int mt = 0; mt < 2; mt++) {
                int r = (m0 + mt * 16 + g) * ST2 + kw + t;
                ahi[mt][0] = smw[HHI + r];
                ahi[mt][1] = smw[HHI + r + 8 * ST2];
                ahi[mt][2] = smw[HHI + r + 4];
                ahi[mt][3] = smw[HHI + r + 8 * ST2 + 4];
                alo[mt][0] = smw[HLO + r];
                alo[mt][1] = smw[HLO + r + 8 * ST2];
                alo[mt][2] = smw[HLO + r + 4];
                alo[mt][3] = smw[HLO + r + 8 * ST2 + 4];
            }
            uint32_t bf[4][2];
            #pragma unroll
            for (int nt = 0; nt < 4; nt++) {
                int rb = (n0 + nt * 8 + g) * ST2 + kw + t;
                bf[nt][0] = smw[W2S + rb]; bf[nt][1] = smw[W2S + rb + 4];
            }
            #pragma unroll
            for (int mt = 0; mt < 2; mt++)
                #pragma unroll
                for (int nt = 0; nt < 4; nt++) {
                    mma16816(acc[mt][nt], ahi[mt], bf[nt]);
                    mma16816(acc[mt][nt], alo[mt], bf[nt]);
                }
        }

        // ---- epilogue: (acc + b2)*C*vl[j] -> out ----
        #pragma unroll
        for (int mt = 0; mt < 2; mt++) {
            int el0 = m0 + mt * 16 + g;        // local edge rows el0, el0+8
            int e0 = tile * 64 + el0;
            int e1 = e0 + 8;
            #pragma unroll
            for (int nt = 0; nt < 4; nt++) {
                int f = n0 + nt * 8 + 2 * t;
                float2 bb = *(const float2*)(b2f + f);
                if (e0 < E) {
                    float Cv = Csf[el0];
                    const float2 vv = *(const float2*)(g_vl + (size_t)Jsi[el0] * 128 + f);
                    float2 o;
                    o.x = (acc[mt][nt][0] + bb.x) * Cv * vv.x;
                    o.y = (acc[mt][nt][1] + bb.y) * Cv * vv.y;
                    *(float2*)(out + (size_t)e0 * 128 + f) = o;
                }
                if (e1 < E) {
                    float Cv = Csf[el0 + 8];
                    const float2 vv = *(const float2*)(g_vl + (size_t)Jsi[el0 + 8] * 128 + f);
                    float2 o;
                    o.x = (acc[mt][nt][2] + bb.x) * Cv * vv.x;
                    o.y = (acc[mt][nt][3] + bb.y) * Cv * vv.y;
                    *(float2*)(out + (size_t)e1 * 128 + f) = o;
                }
            }
        }
    }
}

// ---------------------------------------------------------------------------
extern "C" void kernel_launch(void* const* d_in, const int* in_sizes, int n_in,
                              void* d_out, int out_size)
{
    const float* v          = (const float*)d_in[0];
    const float* dist       = (const float*)d_in[1];
    const float* dist_emb   = (const float*)d_in[2];
    const int*   edge_index = (const int*)d_in[3];   // int32 [2][E]
    const float* lin_w      = (const float*)d_in[4];
    const float* mlp1_w     = (const float*)d_in[5];
    const float* mlp1_b     = (const float*)d_in[6];
    const float* mlp2_w     = (const float*)d_in[7];
    const float* mlp2_b     = (const float*)d_in[8];
    float*       out        = (float*)d_out;

    const int N = in_sizes[0] / 128;
    const int E = in_sizes[1];
    const int ntiles = (E + 63) / 64;

    const size_t smemA = (size_t)(128 * 128 + 128 * 132) * sizeof(float);
    const size_t smemB = (size_t)SMEM_WORDS * 4;     // 108032 B

    cudaFuncSetAttribute(vl_kernel, cudaFuncAttributeMaxDynamicSharedMemorySize, (int)smemA);
    cudaFuncSetAttribute(edge_mma_kernel, cudaFuncAttributeMaxDynamicSharedMemorySize, (int)smemB);

    vl_kernel<<<(N + 127) / 128, 256, smemA>>>(v, lin_w, N);

    int grid = 304;                                  // 2 CTAs / SM
    if (grid > ntiles) grid = ntiles;
    edge_mma_kernel<<<grid, 256, smemB>>>(dist, dist_emb, edge_index,
                                          mlp1_w, mlp1_b, mlp2_w, mlp2_b,
                                          out, E, ntiles);
}

// round 11
// speedup vs baseline: 3.2107x; 1.1039x over previous
#include <cuda_runtime.h>
#include <cuda_fp16.h>
#include <cstdint>

// ---------------------------------------------------------------------------
// update_e: SchNet CFConv edge message — mma.sync fp16 + ldmatrix.
//   C    = 0.5*(cos(pi*d/10)+1)
//   h    = softplus(dist_emb @ mlp1_w^T + b1) - log(2)
//   W    = (h @ mlp2_w^T + b2) * C
//   out  = (v @ lin_w^T)[j] * W
//
// R10: single fp16 operands (no hi/lo split; fp32 accumulate). Calibrated
// error model: 4 rounding sources x ~2.1e-4 each -> ~4.2e-4 total (<1e-3).
// All MMA fragments loaded via ldmatrix.m8n8.x4 (conflict-free: row strides
// 144/272 B == 16 mod 128). Persistent, grid=304, 256 thr (8 warps, 2x4),
// tile = 64 edges x 128 feats, ~80KB SMEM -> 2 CTA/SM.
// ---------------------------------------------------------------------------

#define SHIFT_LN2       0.69314718055994530942f
#define PI_OVER_CUTOFF  0.31415926535897932385f

__device__ float g_vl[50000 * 128];

extern __shared__ uint32_t smw[];

// ---- SMEM word-offsets (edge kernel) ----
static constexpr int ST1 = 36;     // words/row, K=64 fp16 (32 words) + 4 pad
static constexpr int ST2 = 68;     // words/row, K=128 fp16 (64 words) + 4 pad
static constexpr int W1S = 0;                        // [128][36]
static constexpr int W2S = W1S + 128 * ST1;          // [128][68]
static constexpr int EMB = W2S + 128 * ST2;          // [64][36]
static constexpr int HS  = EMB + 64 * ST1;           // [64][68]
static constexpr int B1W = HS + 64 * ST2;            // 128 f32
static constexpr int B2W = B1W + 128;
static constexpr int CSW = B2W + 128;                // 64 f32
static constexpr int JSW = CSW + 64;                 // 64 i32
static constexpr int SMEM_WORDS = JSW + 64;          // 20352 words = 81408 B

// ---------------------------- helpers --------------------------------------
__device__ __forceinline__ float softplus_fast(float x) {
    return (x > 15.f) ? x : __logf(1.f + __expf(x));
}
__device__ __forceinline__ uint32_t cvt2(float x0, float x1) {
    __half2 p = __halves2half2(__float2half(x0), __float2half(x1));
    return *reinterpret_cast<uint32_t*>(&p);
}
__device__ __forceinline__ uint32_t smem_addr(const void* p) {
    uint32_t a;
    asm("{ .reg .u64 t; cvta.to.shared.u64 t, %1; cvt.u32.u64 %0, t; }"
        : "=r"(a) : "l"(p));
    return a;
}
__device__ __forceinline__ void ldm_x4(uint32_t& r0, uint32_t& r1,
                                       uint32_t& r2, uint32_t& r3, uint32_t addr) {
    asm volatile("ldmatrix.sync.aligned.m8n8.x4.shared.b16 {%0,%1,%2,%3}, [%4];"
                 : "=r"(r0), "=r"(r1), "=r"(r2), "=r"(r3) : "r"(addr));
}
__device__ __forceinline__ void mma16816(float d[4], const uint32_t a[4], const uint32_t b[2]) {
    asm volatile(
        "mma.sync.aligned.m16n8k16.row.col.f32.f16.f16.f32 "
        "{%0,%1,%2,%3}, {%4,%5,%6,%7}, {%8,%9}, {%0,%1,%2,%3};"
        : "+f"(d[0]), "+f"(d[1]), "+f"(d[2]), "+f"(d[3])
        : "r"(a[0]), "r"(a[1]), "r"(a[2]), "r"(a[3]), "r"(b[0]), "r"(b[1]));
}

// ------------------------- Kernel A: vl = v @ lin_w^T -----------------------
__global__ void __launch_bounds__(256, 1)
vl_kernel(const float* __restrict__ v, const float* __restrict__ lin_w, int nrows)
{
    float* smem = (float*)smw;
    float* wT = smem;               // [128][128]
    float* a  = smem + 128 * 128;   // [128][132]
    const int tid = threadIdx.x;
    const int r0  = blockIdx.x * 128;

    for (int i = tid; i < 128 * 128; i += 256) {
        int f = i >> 7, k = i & 127;
        wT[k * 128 + f] = lin_w[i];
    }
    for (int i = tid; i < 128 * 128; i += 256) {
        int r = i >> 7, k = i & 127;
        int rg = r0 + r;
        a[r * 132 + k] = (rg < nrows) ? v[(size_t)rg * 128 + k] : 0.f;
    }
    __syncthreads();

    const int tx = tid & 15, ty = tid >> 4;
    const int f0 = tx * 8, rr0 = ty * 8;

    float acc[8][8];
    #pragma unroll
    for (int i = 0; i < 8; i++)
        #pragma unroll
        for (int j = 0; j < 8; j++) acc[i][j] = 0.f;

    #pragma unroll 8
    for (int k = 0; k < 128; k++) {
        float4 b0 = *reinterpret_cast<const float4*>(&wT[k * 128 + f0]);
        float4 b1 = *reinterpret_cast<const float4*>(&wT[k * 128 + f0 + 4]);
        #pragma unroll
        for (int i = 0; i < 8; i++) {
            float av = a[(rr0 + i) * 132 + k];
            acc[i][0] += av * b0.x; acc[i][1] += av * b0.y;
            acc[i][2] += av * b0.z; acc[i][3] += av * b0.w;
            acc[i][4] += av * b1.x; acc[i][5] += av * b1.y;
            acc[i][6] += av * b1.z; acc[i][7] += av * b1.w;
        }
    }

    #pragma unroll
    for (int i = 0; i < 8; i++) {
        int rg = r0 + rr0 + i;
        if (rg < nrows) {
            *reinterpret_cast<float4*>(&g_vl[(size_t)rg * 128 + f0]) =
                make_float4(acc[i][0], acc[i][1], acc[i][2], acc[i][3]);
            *reinterpret_cast<float4*>(&g_vl[(size_t)rg * 128 + f0 + 4]) =
                make_float4(acc[i][4], acc[i][5], acc[i][6], acc[i][7]);
        }
    }
}

// ---------------- Kernel B: persistent mma.sync edge kernel -----------------
__global__ void __launch_bounds__(256, 2)
edge_mma_kernel(const float* __restrict__ dist,
                const float* __restrict__ dist_emb,
                const int* __restrict__ edge_index,   // int32, row 0 = source
                const float* __restrict__ mlp1_w, const float* __restrict__ mlp1_b,
                const float* __restrict__ mlp2_w, const float* __restrict__ mlp2_b,
                float* __restrict__ out, int E, int ntiles)
{
    const int tid  = threadIdx.x;
    const int lane = tid & 31;
    const int wid  = tid >> 5;
    const int g    = lane >> 2;      // group row 0..7
    const int t    = lane & 3;       // thread-in-group 0..3
    const int wm   = wid & 1;        // warp m index (edges: 2)
    const int wn   = wid >> 1;       // warp n index (feats: 4)
    const int m0   = wm * 32;
    const int n0   = wn * 32;

    const uint32_t sbase = smem_addr(smw);

    // ldmatrix lane-address components (canonical x4 mapping):
    // lanes 0-7 -> rows 0-7 (k lo), 8-15 -> rows 8-15 (k lo),
    // 16-23 -> rows 0-7 (k hi), 24-31 -> rows 8-15 (k hi)
    const int sub = lane >> 3, lr = lane & 7;
    const int rowoff = ((sub & 1) << 3) + lr;     // 0..15
    const int kcol   = (sub >> 1) << 2;           // 0 or 4 words

    float* b1f = (float*)(smw + B1W);
    float* b2f = (float*)(smw + B2W);
    float* Csf = (float*)(smw + CSW);
    int*   Jsi = (int*)(smw + JSW);

    // ---- zero padded K-regions once (w1 / emb fp16 cols 50..63 -> 0) ----
    for (int i = tid; i < 128 * ST1; i += 256) smw[W1S + i] = 0;
    for (int i = tid; i < 64 * ST1; i += 256) smw[EMB + i] = 0;
    __syncthreads();

    // ---- stage weights as fp16 (once per CTA) ----
    for (int i = tid; i < 128 * 25; i += 256) {          // w1: 128 x 50
        int f = i / 25, c = i - f * 25;
        float2 w = *(const float2*)(mlp1_w + (size_t)f * 50 + 2 * c);
        smw[W1S + f * ST1 + c] = cvt2(w.x, w.y);
    }
    for (int i = tid; i < 128 * 64; i += 256) {          // w2: 128 x 128
        int f = i >> 6, c = i & 63;
        float2 w = *(const float2*)(mlp2_w + (size_t)f * 128 + 2 * c);
        smw[W2S + f * ST2 + c] = cvt2(w.x, w.y);
    }
    if (tid < 128) { b1f[tid] = mlp1_b[tid]; b2f[tid] = mlp2_b[tid]; }

    // per-warp ldmatrix base addresses (bytes)
    const uint32_t embA = sbase + 4u * (EMB + (m0 + rowoff) * ST1 + kcol);
    const uint32_t w1B  = sbase + 4u * (W1S + (n0 + rowoff) * ST1 + kcol);
    const uint32_t hA   = sbase + 4u * (HS  + (m0 + rowoff) * ST2 + kcol);
    const uint32_t w2B  = sbase + 4u * (W2S + (n0 + rowoff) * ST2 + kcol);

    for (int tile = blockIdx.x; tile < ntiles; tile += gridDim.x) {
        __syncthreads();   // protect CS/JS/EMB/H against prior-tile readers

        // ---- per-edge scalars (64 edges) ----
        if (tid < 64) {
            int e = tile * 64 + tid;
            if (e < E) {
                Csf[tid] = 0.5f * (__cosf(dist[e] * PI_OVER_CUTOFF) + 1.f);
                Jsi[tid] = edge_index[e];
            } else { Csf[tid] = 0.f; Jsi[tid] = 0; }
        }
        // ---- emb tile -> fp16 ----
        for (int i = tid; i < 64 * 25; i += 256) {
            int row = i / 25, c = i - row * 25;
            int e = tile * 64 + row;
            float2 w = (e < E) ? *(const float2*)(dist_emb + (size_t)e * 50 + 2 * c)
                               : make_float2(0.f, 0.f);
            smw[EMB + row * ST1 + c] = cvt2(w.x, w.y);
        }
        __syncthreads();

        // ================= GEMM1: h = emb @ w1^T (K=64) =================
        float acc[2][4][4];
        #pragma unroll
        for (int mt = 0; mt < 2; mt++)
            #pragma unroll
            for (int nt = 0; nt < 4; nt++)
                #pragma unroll
                for (int q = 0; q < 4; q++) acc[mt][nt][q] = 0.f;

        #pragma unroll
        for (int ks = 0; ks < 4; ks++) {
            const uint32_t kb = (uint32_t)(ks * 8) * 4u;  // k-step bytes
            uint32_t a[2][4], b[2][4];
            #pragma unroll
            for (int mt = 0; mt < 2; mt++)
                ldm_x4(a[mt][0], a[mt][1], a[mt][2], a[mt][3],
                       embA + kb + (uint32_t)(mt * 16 * ST1) * 4u);
            #pragma unroll
            for (int np = 0; np < 2; np++)
                ldm_x4(b[np][0], b[np][1], b[np][2], b[np][3],
                       w1B + kb + (uint32_t)(np * 16 * ST1) * 4u);
            #pragma unroll
            for (int mt = 0; mt < 2; mt++)
                #pragma unroll
                for (int np = 0; np < 2; np++) {
                    uint32_t be[2] = { b[np][0], b[np][2] };
                    uint32_t bo[2] = { b[np][1], b[np][3] };
                    mma16816(acc[mt][2 * np],     a[mt], be);
                    mma16816(acc[mt][2 * np + 1], a[mt], bo);
                }
        }

        // ---- softplus(+b1) - ln2 -> fp16 -> h SMEM ----
        #pragma unroll
        for (int mt = 0; mt < 2; mt++) {
            int row0 = m0 + mt * 16 + g;
            #pragma unroll
            for (int nt = 0; nt < 4; nt++) {
                int f = n0 + nt * 8 + 2 * t;
                float bb0 = b1f[f], bb1 = b1f[f + 1];
                int col = (n0 >> 1) + nt * 4 + t;
                smw[HS + row0 * ST2 + col] =
                    cvt2(softplus_fast(acc[mt][nt][0] + bb0) - SHIFT_LN2,
                         softplus_fast(acc[mt][nt][1] + bb1) - SHIFT_LN2);
                smw[HS + (row0 + 8) * ST2 + col] =
                    cvt2(softplus_fast(acc[mt][nt][2] + bb0) - SHIFT_LN2,
                         softplus_fast(acc[mt][nt][3] + bb1) - SHIFT_LN2);
            }
        }
        __syncthreads();

        // ================= GEMM2: W = h @ w2^T (K=128) =================
        #pragma unroll
        for (int mt = 0; mt < 2; mt++)
            #pragma unroll
            for (int nt = 0; nt < 4; nt++)
                #pragma unroll
                for (int q = 0; q < 4; q++) acc[mt][nt][q] = 0.f;

        #pragma unroll
        for (int ks = 0; ks < 8; ks++) {
            const uint32_t kb = (uint32_t)(ks * 8) * 4u;
            uint32_t a[2][4], b[2][4];
            #pragma unroll
            for (int mt = 0; mt < 2; mt++)
                ldm_x4(a[mt][0], a[mt][1], a[mt][2], a[mt][3],
                       hA + kb + (uint32_t)(mt * 16 * ST2) * 4u);
            #pragma unroll
            for (int np = 0; np < 2; np++)
                ldm_x4(b[np][0], b[np][1], b[np][2], b[np][3],
                       w2B + kb + (uint32_t)(np * 16 * ST2) * 4u);
            #pragma unroll
            for (int mt = 0; mt < 2; mt++)
                #pragma unroll
                for (int np = 0; np < 2; np++) {
                    uint32_t be[2] = { b[np][0], b[np][2] };
                    uint32_t bo[2] = { b[np][1], b[np][3] };
                    mma16816(acc[mt][2 * np],     a[mt], be);
                    mma16816(acc[mt][2 * np + 1], a[mt], bo);
                }
        }

        // ---- epilogue: (acc + b2)*C*vl[j] -> out ----
        #pragma unroll
        for (int mt = 0; mt < 2; mt++) {
            int el0 = m0 + mt * 16 + g;        // local edge rows el0, el0+8
            int e0 = tile * 64 + el0;
            int e1 = e0 + 8;
            #pragma unroll
            for (int nt = 0; nt < 4; nt++) {
                int f = n0 + nt * 8 + 2 * t;
                float2 bb = *(const float2*)(b2f + f);
                if (e0 < E) {
                    float Cv = Csf[el0];
                    const float2 vv = *(const float2*)(g_vl + (size_t)Jsi[el0] * 128 + f);
                    float2 o;
                    o.x = (acc[mt][nt][0] + bb.x) * Cv * vv.x;
                    o.y = (acc[mt][nt][1] + bb.y) * Cv * vv.y;
                    *(float2*)(out + (size_t)e0 * 128 + f) = o;
                }
                if (e1 < E) {
                    float Cv = Csf[el0 + 8];
                    const float2 vv = *(const float2*)(g_vl + (size_t)Jsi[el0 + 8] * 128 + f);
                    float2 o;
                    o.x = (acc[mt][nt][2] + bb.x) * Cv * vv.x;
                    o.y = (acc[mt][nt][3] + bb.y) * Cv * vv.y;
                    *(float2*)(out + (size_t)e1 * 128 + f) = o;
                }
            }
        }
    }
}

// ---------------------------------------------------------------------------
extern "C" void kernel_launch(void* const* d_in, const int* in_sizes, int n_in,
                              void* d_out, int out_size)
{
    const float* v          = (const float*)d_in[0];
    const float* dist       = (const float*)d_in[1];
    const float* dist_emb   = (const float*)d_in[2];
    const int*   edge_index = (const int*)d_in[3];   // int32 [2][E]
    const float* lin_w      = (const float*)d_in[4];
    const float* mlp1_w     = (const float*)d_in[5];
    const float* mlp1_b     = (const float*)d_in[6];
    const float* mlp2_w     = (const float*)d_in[7];
    const float* mlp2_b     = (const float*)d_in[8];
    float*       out        = (float*)d_out;

    const int N = in_sizes[0] / 128;
    const int E = in_sizes[1];
    const int ntiles = (E + 63) / 64;

    const size_t smemA = (size_t)(128 * 128 + 128 * 132) * sizeof(float);
    const size_t smemB = (size_t)SMEM_WORDS * 4;     // 81408 B

    cudaFuncSetAttribute(vl_kernel, cudaFuncAttributeMaxDynamicSharedMemorySize, (int)smemA);
    cudaFuncSetAttribute(edge_mma_kernel, cudaFuncAttributeMaxDynamicSharedMemorySize, (int)smemB);

    vl_kernel<<<(N + 127) / 128, 256, smemA>>>(v, lin_w, N);

    int grid = 304;                                  // 2 CTAs / SM
    if (grid > ntiles) grid = ntiles;
    edge_mma_kernel<<<grid, 256, smemB>>>(dist, dist_emb, edge_index,
                                          mlp1_w, mlp1_b, mlp2_w, mlp2_b,
                                          out, E, ntiles);
}

// round 12
// speedup vs baseline: 3.2846x; 1.0230x over previous
#include <cuda_runtime.h>
#include <cuda_fp16.h>
#include <cstdint>

// ---------------------------------------------------------------------------
// update_e: SchNet CFConv edge message — fp16 mma.sync + ldmatrix + cp.async.
//   C    = 0.5*(cos(pi*d/10)+1)
//   h    = softplus(dist_emb @ mlp1_w^T + b1) - log(2)
//   W    = (h @ mlp2_w^T + b2) * C
//   out  = (v @ lin_w^T)[j] * W
//
// R12: latency-hiding restructure. Persistent kernel, 512 thr (16 warps,
// 4x4 grid, 32x32 warp tiles), tile = 128 edges. Double-buffered cp.async
// prefetch of emb/dist/idx (tile k+1 loads during tile k compute); vl[j]
// gather via cp.async into SMEM issued at tile start, consumed at epilogue.
// GEMM math identical to R11 (fp16 operands, fp32 accum, rel_err 4.2e-4).
// ---------------------------------------------------------------------------

#define SHIFT_LN2       0.69314718055994530942f
#define PI_OVER_CUTOFF  0.31415926535897932385f

__device__ float g_vl[50000 * 128];

extern __shared__ uint32_t smw[];

// ---- SMEM word-offsets (edge kernel) ----
static constexpr int ST1 = 36;     // W1 row stride (words): K=64 fp16 + pad
static constexpr int ST2 = 68;     // W2/H row stride (words): K=128 fp16 + pad
static constexpr int STE = 68;     // EMB fp32 row stride (floats): 50 data + pad
static constexpr int STV = 132;    // VL fp32 row stride
static constexpr int W1S   = 0;                       // [128][36] fp16x2
static constexpr int W2S   = W1S + 128 * ST1;         // [128][68]
static constexpr int EMB0  = W2S + 128 * ST2;         // [128][68] fp32
static constexpr int EMB1  = EMB0 + 128 * STE;
static constexpr int HS    = EMB1 + 128 * STE;        // [128][68] fp16x2
static constexpr int VLS   = HS + 128 * ST2;          // [128][132] fp32
static constexpr int B1W   = VLS + 128 * STV;         // 128 f32
static constexpr int B2W   = B1W + 128;
static constexpr int CSW   = B2W + 128;               // 128 f32
static constexpr int DIST0 = CSW + 128;               // 128 f32 x2
static constexpr int DIST1 = DIST0 + 128;
static constexpr int IDX0  = DIST1 + 128;             // 128 i32 x2
static constexpr int IDX1  = IDX0 + 128;
static constexpr int SMEM_WORDS = IDX1 + 128;         // 57216 w = 228864 B

// ---------------------------- helpers --------------------------------------
__device__ __forceinline__ float softplus_fast(float x) {
    return (x > 15.f) ? x : __logf(1.f + __expf(x));
}
__device__ __forceinline__ uint32_t cvt2(float x0, float x1) {
    __half2 p = __halves2half2(__float2half(x0), __float2half(x1));
    return *reinterpret_cast<uint32_t*>(&p);
}
__device__ __forceinline__ uint32_t smem_addr(const void* p) {
    uint32_t a;
    asm("{ .reg .u64 t; cvta.to.shared.u64 t, %1; cvt.u32.u64 %0, t; }"
        : "=r"(a) : "l"(p));
    return a;
}
__device__ __forceinline__ void ldm_x4(uint32_t& r0, uint32_t& r1,
                                       uint32_t& r2, uint32_t& r3, uint32_t addr) {
    asm volatile("ldmatrix.sync.aligned.m8n8.x4.shared.b16 {%0,%1,%2,%3}, [%4];"
                 : "=r"(r0), "=r"(r1), "=r"(r2), "=r"(r3) : "r"(addr));
}
__device__ __forceinline__ void mma16816(float d[4], const uint32_t a[4], const uint32_t b[2]) {
    asm volatile(
        "mma.sync.aligned.m16n8k16.row.col.f32.f16.f16.f32 "
        "{%0,%1,%2,%3}, {%4,%5,%6,%7}, {%8,%9}, {%0,%1,%2,%3};"
        : "+f"(d[0]), "+f"(d[1]), "+f"(d[2]), "+f"(d[3])
        : "r"(a[0]), "r"(a[1]), "r"(a[2]), "r"(a[3]), "r"(b[0]), "r"(b[1]));
}
__device__ __forceinline__ void cp16(uint32_t dst, const void* src) {
    asm volatile("cp.async.ca.shared.global [%0], [%1], 16;" :: "r"(dst), "l"(src));
}
__device__ __forceinline__ void cp8(uint32_t dst, const void* src) {
    asm volatile("cp.async.ca.shared.global [%0], [%1], 8;" :: "r"(dst), "l"(src));
}
__device__ __forceinline__ void cp4(uint32_t dst, const void* src) {
    asm volatile("cp.async.ca.shared.global [%0], [%1], 4;" :: "r"(dst), "l"(src));
}
#define CP_COMMIT() asm volatile("cp.async.commit_group;" ::: "memory")
#define CP_WAIT(n)  asm volatile("cp.async.wait_group %0;" :: "n"(n) : "memory")

// ------------------------- Kernel A: vl = v @ lin_w^T -----------------------
__global__ void __launch_bounds__(256, 1)
vl_kernel(const float* __restrict__ v, const float* __restrict__ lin_w, int nrows)
{
    float* smem = (float*)smw;
    float* wT = smem;               // [128][128]
    float* a  = smem + 128 * 128;   // [128][132]
    const int tid = threadIdx.x;
    const int r0  = blockIdx.x * 128;

    for (int i = tid; i < 128 * 128; i += 256) {
        int f = i >> 7, k = i & 127;
        wT[k * 128 + f] = lin_w[i];
    }
    for (int i = tid; i < 128 * 128; i += 256) {
        int r = i >> 7, k = i & 127;
        int rg = r0 + r;
        a[r * 132 + k] = (rg < nrows) ? v[(size_t)rg * 128 + k] : 0.f;
    }
    __syncthreads();

    const int tx = tid & 15, ty = tid >> 4;
    const int f0 = tx * 8, rr0 = ty * 8;

    float acc[8][8];
    #pragma unroll
    for (int i = 0; i < 8; i++)
        #pragma unroll
        for (int j = 0; j < 8; j++) acc[i][j] = 0.f;

    #pragma unroll 8
    for (int k = 0; k < 128; k++) {
        float4 b0 = *reinterpret_cast<const float4*>(&wT[k * 128 + f0]);
        float4 b1 = *reinterpret_cast<const float4*>(&wT[k * 128 + f0 + 4]);
        #pragma unroll
        for (int i = 0; i < 8; i++) {
            float av = a[(rr0 + i) * 132 + k];
            acc[i][0] += av * b0.x; acc[i][1] += av * b0.y;
            acc[i][2] += av * b0.z; acc[i][3] += av * b0.w;
            acc[i][4] += av * b1.x; acc[i][5] += av * b1.y;
            acc[i][6] += av * b1.z; acc[i][7] += av * b1.w;
        }
    }

    #pragma unroll
    for (int i = 0; i < 8; i++) {
        int rg = r0 + rr0 + i;
        if (rg < nrows) {
            *reinterpret_cast<float4*>(&g_vl[(size_t)rg * 128 + f0]) =
                make_float4(acc[i][0], acc[i][1], acc[i][2], acc[i][3]);
            *reinterpret_cast<float4*>(&g_vl[(size_t)rg * 128 + f0 + 4]) =
                make_float4(acc[i][4], acc[i][5], acc[i][6], acc[i][7]);
        }
    }
}

// ---------------- Kernel B: persistent pipelined edge kernel ----------------
__global__ void __launch_bounds__(512, 1)
edge_mma_kernel(const float* __restrict__ dist,
                const float* __restrict__ dist_emb,
                const int* __restrict__ edge_index,   // int32, row 0 = source
                const float* __restrict__ mlp1_w, const float* __restrict__ mlp1_b,
                const float* __restrict__ mlp2_w, const float* __restrict__ mlp2_b,
                float* __restrict__ out, int E, int ntiles)
{
    const int tid  = threadIdx.x;
    const int lane = tid & 31;
    const int wid  = tid >> 5;
    const int g    = lane >> 2;      // group row 0..7
    const int t    = lane & 3;       // thread-in-group 0..3
    const int wm   = wid & 3;        // warp m index (edges: 4)
    const int wn   = wid >> 2;       // warp n index (feats: 4)
    const int m0   = wm * 32;
    const int n0   = wn * 32;

    const uint32_t sbase = smem_addr(smw);

    // ldmatrix lane-address mapping
    const int sub = lane >> 3, lr = lane & 7;
    const int rowoff = ((sub & 1) << 3) + lr;     // 0..15
    const int kcol   = (sub >> 1) << 2;           // 0 or 4 words

    float* b1f = (float*)(smw + B1W);
    float* b2f = (float*)(smw + B2W);
    float* Csf = (float*)(smw + CSW);

    // ---- zero regions that are read-before-full-write ----
    for (int i = tid; i < 128 * ST1; i += 512) smw[W1S + i] = 0;       // W1 K-pad
    for (int i = tid; i < 2 * 128 * STE; i += 512) smw[EMB0 + i] = 0;  // EMB bufs
    if (tid < 128) { smw[IDX0 + tid] = 0; smw[IDX1 + tid] = 0; }
    __syncthreads();

    // ---- stage weights as fp16 (once per CTA) ----
    for (int i = tid; i < 128 * 25; i += 512) {          // w1: 128 x 50
        int f = i / 25, c = i - f * 25;
        float2 w = *(const float2*)(mlp1_w + (size_t)f * 50 + 2 * c);
        smw[W1S + f * ST1 + c] = cvt2(w.x, w.y);
    }
    for (int i = tid; i < 128 * 64; i += 512) {          // w2: 128 x 128
        int f = i >> 6, c = i & 63;
        float2 w = *(const float2*)(mlp2_w + (size_t)f * 128 + 2 * c);
        smw[W2S + f * ST2 + c] = cvt2(w.x, w.y);
    }
    if (tid < 128) { b1f[tid] = mlp1_b[tid]; b2f[tid] = mlp2_b[tid]; }
    __syncthreads();

    // prefetch helper (inlined via lambda-like macro using locals)
    const int prow = tid >> 2;        // 0..127  (emb: 4 threads/row)
    const int pq   = tid & 3;

    // ---- prologue: prefetch first tile into buf 0 ----
    {
        int tile0 = blockIdx.x;
        if (tile0 < ntiles) {
            int e = tile0 * 128 + prow;
            if (e < E) {
                const float* src = dist_emb + (size_t)e * 50;
                uint32_t dst = sbase + 4u * (uint32_t)(EMB0 + prow * STE);
                for (int c = pq; c < 25; c += 4) cp8(dst + c * 8, src + c * 2);
            }
            if (tid < 32) {
                int e0 = tile0 * 128 + tid * 4;
                if (e0 + 3 < E) cp16(sbase + 4u * (uint32_t)(DIST0 + tid * 4), dist + e0);
                else for (int k = 0; k < 4; k++)
                    if (e0 + k < E) cp4(sbase + 4u * (uint32_t)(DIST0 + tid * 4 + k), dist + e0 + k);
            } else if (tid < 64) {
                int l2 = tid - 32;
                int e0 = tile0 * 128 + l2 * 4;
                if (e0 + 3 < E) cp16(sbase + 4u * (uint32_t)(IDX0 + l2 * 4), edge_index + e0);
                else for (int k = 0; k < 4; k++)
                    if (e0 + k < E) cp4(sbase + 4u * (uint32_t)(IDX0 + l2 * 4 + k), edge_index + e0 + k);
            }
        }
        CP_COMMIT();
    }

    int buf = 0;
    for (int tile = blockIdx.x; tile < ntiles; tile += gridDim.x) {
        CP_WAIT(0);                 // this tile's emb/dist/idx landed
        __syncthreads();            // barrier TOP

        const int embb  = buf ? EMB1 : EMB0;
        const int distb = buf ? DIST1 : DIST0;
        const int idxb  = buf ? IDX1 : IDX0;

        // ---- per-edge cutoff ----
        if (tid < 128) {
            float d = ((const float*)(smw + distb))[tid];
            Csf[tid] = 0.5f * (__cosf(d * PI_OVER_CUTOFF) + 1.f);
        }

        // ---- vl gather via cp.async (group V) ----
        {
            int j = ((const int*)(smw + idxb))[prow];
            const float* src = g_vl + (size_t)j * 128 + pq * 32;
            uint32_t dst = sbase + 4u * (uint32_t)(VLS + prow * STV + pq * 32);
            #pragma unroll
            for (int i = 0; i < 8; i++) cp16(dst + i * 16, src + i * 4);
        }
        CP_COMMIT();                // group V

        // ---- prefetch next tile (group P, possibly empty) ----
        {
            int tn = tile + gridDim.x;
            if (tn < ntiles) {
                const int embn  = buf ? EMB0 : EMB1;
                const int distn = buf ? DIST0 : DIST1;
                const int idxn  = buf ? IDX0 : IDX1;
                int e = tn * 128 + prow;
                if (e < E) {
                    const float* src = dist_emb + (size_t)e * 50;
                    uint32_t dst = sbase + 4u * (uint32_t)(embn + prow * STE);
                    for (int c = pq; c < 25; c += 4) cp8(dst + c * 8, src + c * 2);
                }
                if (tid < 32) {
                    int e0 = tn * 128 + tid * 4;
                    if (e0 + 3 < E) cp16(sbase + 4u * (uint32_t)(distn + tid * 4), dist + e0);
                    else for (int k = 0; k < 4; k++)
                        if (e0 + k < E) cp4(sbase + 4u * (uint32_t)(distn + tid * 4 + k), dist + e0 + k);
                } else if (tid < 64) {
                    int l2 = tid - 32;
                    int e0 = tn * 128 + l2 * 4;
                    if (e0 + 3 < E) cp16(sbase + 4u * (uint32_t)(idxn + l2 * 4), edge_index + e0);
                    else for (int k = 0; k < 4; k++)
                        if (e0 + k < E) cp4(sbase + 4u * (uint32_t)(idxn + l2 * 4 + k), edge_index + e0 + k);
                }
            }
            CP_COMMIT();            // group P
        }

        // ================= GEMM1: h = emb @ w1^T (K=64) =================
        float acc[2][4][4];
        #pragma unroll
        for (int mt = 0; mt < 2; mt++)
            #pragma unroll
            for (int nt = 0; nt < 4; nt++)
                #pragma unroll
                for (int q = 0; q < 4; q++) acc[mt][nt][q] = 0.f;

        const uint32_t w1B = sbase + 4u * (uint32_t)(W1S + (n0 + rowoff) * ST1 + kcol);
        #pragma unroll
        for (int ks = 0; ks < 4; ks++) {
            const int kp2 = (ks * 8 + t) * 2;     // float index within row
            uint32_t a[2][4], b[2][4];
            const float* eb = (const float*)(smw + embb);
            #pragma unroll
            for (int mt = 0; mt < 2; mt++) {
                int r = m0 + mt * 16 + g;
                float2 p0 = *(const float2*)(eb + r * STE + kp2);
                float2 p1 = *(const float2*)(eb + (r + 8) * STE + kp2);
                float2 p2 = *(const float2*)(eb + r * STE + kp2 + 8);
                float2 p3 = *(const float2*)(eb + (r + 8) * STE + kp2 + 8);
                a[mt][0] = cvt2(p0.x, p0.y);
                a[mt][1] = cvt2(p1.x, p1.y);
                a[mt][2] = cvt2(p2.x, p2.y);
                a[mt][3] = cvt2(p3.x, p3.y);
            }
            const uint32_t kb = (uint32_t)(ks * 8) * 4u;
            #pragma unroll
            for (int np = 0; np < 2; np++)
                ldm_x4(b[np][0], b[np][1], b[np][2], b[np][3],
                       w1B + kb + (uint32_t)(np * 16 * ST1) * 4u);
            #pragma unroll
            for (int mt = 0; mt < 2; mt++)
                #pragma unroll
                for (int np = 0; np < 2; np++) {
                    uint32_t be[2] = { b[np][0], b[np][2] };
                    uint32_t bo[2] = { b[np][1], b[np][3] };
                    mma16816(acc[mt][2 * np],     a[mt], be);
                    mma16816(acc[mt][2 * np + 1], a[mt], bo);
                }
        }

        // ---- softplus(+b1) - ln2 -> fp16 -> h SMEM ----
        #pragma unroll
        for (int mt = 0; mt < 2; mt++) {
            int row0 = m0 + mt * 16 + g;
            #pragma unroll
            for (int nt = 0; nt < 4; nt++) {
                int f = n0 + nt * 8 + 2 * t;
                float bb0 = b1f[f], bb1 = b1f[f + 1];
                int col = (n0 >> 1) + nt * 4 + t;
                smw[HS + row0 * ST2 + col] =
                    cvt2(softplus_fast(acc[mt][nt][0] + bb0) - SHIFT_LN2,
                         softplus_fast(acc[mt][nt][1] + bb1) - SHIFT_LN2);
                smw[HS + (row0 + 8) * ST2 + col] =
                    cvt2(softplus_fast(acc[mt][nt][2] + bb0) - SHIFT_LN2,
                         softplus_fast(acc[mt][nt][3] + bb1) - SHIFT_LN2);
            }
        }
        __syncthreads();            // barrier B

        // ================= GEMM2: W = h @ w2^T (K=128) =================
        #pragma unroll
        for (int mt = 0; mt < 2; mt++)
            #pragma unroll
            for (int nt = 0; nt < 4; nt++)
                #pragma unroll
                for (int q = 0; q < 4; q++) acc[mt][nt][q] = 0.f;

        const uint32_t hA  = sbase + 4u * (uint32_t)(HS  + (m0 + rowoff) * ST2 + kcol);
        const uint32_t w2B = sbase + 4u * (uint32_t)(W2S + (n0 + rowoff) * ST2 + kcol);
        #pragma unroll
        for (int ks = 0; ks < 8; ks++) {
            const uint32_t kb = (uint32_t)(ks * 8) * 4u;
            uint32_t a[2][4], b[2][4];
            #pragma unroll
            for (int mt = 0; mt < 2; mt++)
                ldm_x4(a[mt][0], a[mt][1], a[mt][2], a[mt][3],
                       hA + kb + (uint32_t)(mt * 16 * ST2) * 4u);
            #pragma unroll
            for (int np = 0; np < 2; np++)
                ldm_x4(b[np][0], b[np][1], b[np][2], b[np][3],
                       w2B + kb + (uint32_t)(np * 16 * ST2) * 4u);
            #pragma unroll
            for (int mt = 0; mt < 2; mt++)
                #pragma unroll
                for (int np = 0; np < 2; np++) {
                    uint32_t be[2] = { b[np][0], b[np][2] };
                    uint32_t bo[2] = { b[np][1], b[np][3] };
                    mma16816(acc[mt][2 * np],     a[mt], be);
                    mma16816(acc[mt][2 * np + 1], a[mt], bo);
                }
        }

        CP_WAIT(1);                 // group V done (P may still fly)
        __syncthreads();            // barrier C — vl tile visible to all

        // ---- epilogue: (acc + b2)*C*vl_smem -> out ----
        const float* vls = (const float*)(smw + VLS);
        #pragma unroll
        for (int mt = 0; mt < 2; mt++) {
            int el0 = m0 + mt * 16 + g;
            int e0 = tile * 128 + el0;
            int e1 = e0 + 8;
            #pragma unroll
            for (int nt = 0; nt < 4; nt++) {
                int f = n0 + nt * 8 + 2 * t;
                float2 bb = *(const float2*)(b2f + f);
                if (e0 < E) {
                    float Cv = Csf[el0];
                    float2 vv = *(const float2*)(vls + el0 * STV + f);
                    float2 o;
                    o.x = (acc[mt][nt][0] + bb.x) * Cv * vv.x;
                    o.y = (acc[mt][nt][1] + bb.y) * Cv * vv.y;
                    *(float2*)(out + (size_t)e0 * 128 + f) = o;
                }
                if (e1 < E) {
                    float Cv = Csf[el0 + 8];
                    float2 vv = *(const float2*)(vls + (el0 + 8) * STV + f);
                    float2 o;
                    o.x = (acc[mt][nt][2] + bb.x) * Cv * vv.x;
                    o.y = (acc[mt][nt][3] + bb.y) * Cv * vv.y;
                    *(float2*)(out + (size_t)e1 * 128 + f) = o;
                }
            }
        }
        buf ^= 1;
    }
}

// ---------------------------------------------------------------------------
extern "C" void kernel_launch(void* const* d_in, const int* in_sizes, int n_in,
                              void* d_out, int out_size)
{
    const float* v          = (const float*)d_in[0];
    const float* dist       = (const float*)d_in[1];
    const float* dist_emb   = (const float*)d_in[2];
    const int*   edge_index = (const int*)d_in[3];   // int32 [2][E]
    const float* lin_w      = (const float*)d_in[4];
    const float* mlp1_w     = (const float*)d_in[5];
    const float* mlp1_b     = (const float*)d_in[6];
    const float* mlp2_w     = (const float*)d_in[7];
    const float* mlp2_b     = (const float*)d_in[8];
    float*       out        = (float*)d_out;

    const int N = in_sizes[0] / 128;
    const int E = in_sizes[1];
    const int ntiles = (E + 127) / 128;

    const size_t smemA = (size_t)(128 * 128 + 128 * 132) * sizeof(float);
    const size_t smemB = (size_t)SMEM_WORDS * 4;     // 228864 B

    cudaFuncSetAttribute(vl_kernel, cudaFuncAttributeMaxDynamicSharedMemorySize, (int)smemA);
    cudaFuncSetAttribute(edge_mma_kernel, cudaFuncAttributeMaxDynamicSharedMemorySize, (int)smemB);

    vl_kernel<<<(N + 127) / 128, 256, smemA>>>(v, lin_w, N);

    int grid = 152;                                  // 1 CTA / SM, persistent
    if (grid > ntiles) grid = ntiles;
    edge_mma_kernel<<<grid, 512, smemB>>>(dist, dist_emb, edge_index,
                                          mlp1_w, mlp1_b, mlp2_w, mlp2_b,
                                          out, E, ntiles);
}

// round 15
// speedup vs baseline: 5.5555x; 1.6914x over previous
#include <cuda_runtime.h>
#include <cuda_fp16.h>
#include <cstdint>

// ---------------------------------------------------------------------------
// update_e: SchNet CFConv edge message — fp16 mma.sync, register-resident h.
//   C    = 0.5*(cos(pi*d/10)+1)
//   h    = softplus(dist_emb @ mlp1_w^T + b1) - log(2)
//   W    = (h @ mlp2_w^T + b2) * C
//   out  = (v @ lin_w^T)[j] * W
//
// R13: warp-autonomous design. Each warp owns 16 edges x 128 feats:
//   - emb via per-warp double-buffered cp.async (no cross-warp deps)
//   - GEMM1 acc fragments == GEMM2 A fragments (h stays in registers:
//     no H SMEM store, no GEMM2-A ldmatrix, no inter-GEMM barrier)
//   - NO __syncthreads in the main loop at all; 16 warps/SM drift freely
//   - weights (fp16, ldmatrix layout) staged once; vl[j]/out direct LDG/STG
// 2 CTAs x 256 thr per SM. Math identical to R11/R12 (rel_err 4.2e-4).
// ---------------------------------------------------------------------------

#define SHIFT_LN2       0.69314718055994530942f
#define PI_OVER_CUTOFF  0.31415926535897932385f

__device__ float g_vl[50000 * 128];

extern __shared__ uint32_t smw[];

// ---- SMEM word-offsets (edge kernel) ----
static constexpr int ST1 = 36;     // W1 row stride (words): 32 data + 4 pad
static constexpr int ST2 = 68;     // W2 row stride (words): 64 data + 4 pad
static constexpr int STE = 54;     // emb fp32 row stride (floats): 50 + 4 pad
static constexpr int W1S = 0;                        // [128][36] fp16x2
static constexpr int W2S = W1S + 128 * ST1;          // [128][68] fp16x2
static constexpr int B1W = W2S + 128 * ST2;          // 128 f32
static constexpr int B2W = B1W + 128;                // 128 f32
static constexpr int EMBS = B2W + 128;               // 8 warps x 2 bufs x [16][54] f32
static constexpr int EMBBUF = 16 * STE;              // 864 words per buffer
static constexpr int SMEM_WORDS = EMBS + 8 * 2 * EMBBUF;  // 27392 w = 109568 B

// ---------------------------- helpers --------------------------------------
__device__ __forceinline__ float softplus_fast(float x) {
    // inputs here are O(10) at most; no overflow guard needed (<88)
    return __logf(1.f + __expf(x));
}
__device__ __forceinline__ uint32_t cvt2(float x0, float x1) {
    __half2 p = __halves2half2(__float2half(x0), __float2half(x1));
    return *reinterpret_cast<uint32_t*>(&p);
}
__device__ __forceinline__ uint32_t smem_addr(const void* p) {
    uint32_t a;
    asm("{ .reg .u64 t; cvta.to.shared.u64 t, %1; cvt.u32.u64 %0, t; }"
        : "=r"(a) : "l"(p));
    return a;
}
__device__ __forceinline__ void ldm_x4(uint32_t& r0, uint32_t& r1,
                                       uint32_t& r2, uint32_t& r3, uint32_t addr) {
    asm volatile("ldmatrix.sync.aligned.m8n8.x4.shared.b16 {%0,%1,%2,%3}, [%4];"
                 : "=r"(r0), "=r"(r1), "=r"(r2), "=r"(r3) : "r"(addr));
}
__device__ __forceinline__ void mma16816(float d[4], const uint32_t a[4], const uint32_t b[2]) {
    asm volatile(
        "mma.sync.aligned.m16n8k16.row.col.f32.f16.f16.f32 "
        "{%0,%1,%2,%3}, {%4,%5,%6,%7}, {%8,%9}, {%0,%1,%2,%3};"
        : "+f"(d[0]), "+f"(d[1]), "+f"(d[2]), "+f"(d[3])
        : "r"(a[0]), "r"(a[1]), "r"(a[2]), "r"(a[3]), "r"(b[0]), "r"(b[1]));
}
__device__ __forceinline__ void cp8(uint32_t dst, const void* src) {
    asm volatile("cp.async.ca.shared.global [%0], [%1], 8;" :: "r"(dst), "l"(src));
}
#define CP_COMMIT() asm volatile("cp.async.commit_group;" ::: "memory")
#define CP_WAIT(n)  asm volatile("cp.async.wait_group %0;" :: "n"(n) : "memory")

// ------------------------- Kernel A: vl = v @ lin_w^T -----------------------
__global__ void __launch_bounds__(256, 1)
vl_kernel(const float* __restrict__ v, const float* __restrict__ lin_w, int nrows)
{
    float* smem = (float*)smw;
    float* wT = smem;               // [128][128]
    float* a  = smem + 128 * 128;   // [128][132]
    const int tid = threadIdx.x;
    const int r0  = blockIdx.x * 128;

    for (int i = tid; i < 128 * 128; i += 256) {
        int f = i >> 7, k = i & 127;
        wT[k * 128 + f] = lin_w[i];
    }
    for (int i = tid; i < 128 * 128; i += 256) {
        int r = i >> 7, k = i & 127;
        int rg = r0 + r;
        a[r * 132 + k] = (rg < nrows) ? v[(size_t)rg * 128 + k] : 0.f;
    }
    __syncthreads();

    const int tx = tid & 15, ty = tid >> 4;
    const int f0 = tx * 8, rr0 = ty * 8;

    float acc[8][8];
    #pragma unroll
    for (int i = 0; i < 8; i++)
        #pragma unroll
        for (int j = 0; j < 8; j++) acc[i][j] = 0.f;

    #pragma unroll 8
    for (int k = 0; k < 128; k++) {
        float4 b0 = *reinterpret_cast<const float4*>(&wT[k * 128 + f0]);
        float4 b1 = *reinterpret_cast<const float4*>(&wT[k * 128 + f0 + 4]);
        #pragma unroll
        for (int i = 0; i < 8; i++) {
            float av = a[(rr0 + i) * 132 + k];
            acc[i][0] += av * b0.x; acc[i][1] += av * b0.y;
            acc[i][2] += av * b0.z; acc[i][3] += av * b0.w;
            acc[i][4] += av * b1.x; acc[i][5] += av * b1.y;
            acc[i][6] += av * b1.z; acc[i][7] += av * b1.w;
        }
    }

    #pragma unroll
    for (int i = 0; i < 8; i++) {
        int rg = r0 + rr0 + i;
        if (rg < nrows) {
            *reinterpret_cast<float4*>(&g_vl[(size_t)rg * 128 + f0]) =
                make_float4(acc[i][0], acc[i][1], acc[i][2], acc[i][3]);
            *reinterpret_cast<float4*>(&g_vl[(size_t)rg * 128 + f0 + 4]) =
                make_float4(acc[i][4], acc[i][5], acc[i][6], acc[i][7]);
        }
    }
}

// -------------- Kernel B: warp-autonomous persistent edge kernel ------------
__global__ void __launch_bounds__(256, 2)
edge_mma_kernel(const float* __restrict__ dist,
                const float* __restrict__ dist_emb,
                const int* __restrict__ edge_index,   // int32, row 0 = source
                const float* __restrict__ mlp1_w, const float* __restrict__ mlp1_b,
                const float* __restrict__ mlp2_w, const float* __restrict__ mlp2_b,
                float* __restrict__ out, int E, int ngroups)
{
    const int tid  = threadIdx.x;
    const int lane = tid & 31;
    const int wid  = tid >> 5;       // 0..7
    const int g    = lane >> 2;      // 0..7
    const int t    = lane & 3;       // 0..3

    const uint32_t sbase = smem_addr(smw);

    // ldmatrix lane addressing (x4: 16 rows x 16 fp16 cols)
    const int sub = lane >> 3, lr = lane & 7;
    const int rowoff = ((sub & 1) << 3) + lr;     // 0..15
    const int kcol   = (sub >> 1) << 2;           // 0 or 4 words

    float* b1f = (float*)(smw + B1W);
    float* b2f = (float*)(smw + B2W);

    // ---- zero W1 K-pad (k halves 50..63 must be 0) ----
    for (int i = tid; i < 128 * ST1; i += 256) smw[W1S + i] = 0;
    __syncthreads();

    // ---- stage weights as fp16 (once per CTA) ----
    for (int i = tid; i < 128 * 25; i += 256) {          // w1: 128 x 50
        int f = i / 25, c = i - f * 25;
        float2 w = *(const float2*)(mlp1_w + (size_t)f * 50 + 2 * c);
        smw[W1S + f * ST1 + c] = cvt2(w.x, w.y);
    }
    for (int i = tid; i < 128 * 64; i += 256) {          // w2: 128 x 128
        int f = i >> 6, c = i & 63;
        float2 w = *(const float2*)(mlp2_w + (size_t)f * 128 + 2 * c);
        smw[W2S + f * ST2 + c] = cvt2(w.x, w.y);
    }
    if (tid < 128) { b1f[tid] = mlp1_b[tid]; b2f[tid] = mlp2_b[tid]; }
    __syncthreads();
    // ======= main loop is barrier-free: all mutable SMEM is warp-private ====

    const int embW = EMBS + wid * 2 * EMBBUF;     // this warp's buffers
    const int gwid    = blockIdx.x * 8 + wid;
    const int gstride = gridDim.x * 8;

    // prefetch lane assignment: 2 lanes per row
    const int pr = lane & 15;            // row 0..15
    const int ph = lane >> 4;            // half 0/1: words [0,24) / [24,50)

    // ---- prologue: prefetch first group into buf 0 ----
    {
        int e = gwid * 16 + pr;
        if (gwid < ngroups && e < E) {
            const float* src = dist_emb + (size_t)e * 50 + ph * 24;
            uint32_t dst = sbase + 4u * (uint32_t)(embW + pr * STE + ph * 24);
            int nc = ph ? 13 : 12;
            for (int c = 0; c < nc; c++) cp8(dst + c * 8, src + c * 2);
        }
    }
    CP_COMMIT();

    const uint32_t w1B = sbase + 4u * (uint32_t)(W1S + rowoff * ST1 + kcol);
    const uint32_t w2B = sbase + 4u * (uint32_t)(W2S + rowoff * ST2 + kcol);

    int buf = 0;
    for (int grp = gwid; grp < ngroups; grp += gstride) {
        // ---- prefetch next group into other buffer ----
        {
            int gn = grp + gstride;
            int e = gn * 16 + pr;
            if (gn < ngroups && e < E) {
                const float* src = dist_emb + (size_t)e * 50 + ph * 24;
                uint32_t dst = sbase + 4u * (uint32_t)(embW + (buf ^ 1) * EMBBUF + pr * STE + ph * 24);
                int nc = ph ? 13 : 12;
                for (int c = 0; c < nc; c++) cp8(dst + c * 8, src + c * 2);
            }
        }
        CP_COMMIT();
        CP_WAIT(1);            // current buffer's data landed
        __syncwarp();          // cross-lane visibility within warp

        // ---- per-edge scalars (registers, redundant across t lanes) ----
        const int e0 = grp * 16 + g;
        const int e1 = e0 + 8;
        float C0 = 0.f, C1 = 0.f;
        int j0 = 0, j1 = 0;
        if (e0 < E) { C0 = 0.5f * (__cosf(dist[e0] * PI_OVER_CUTOFF) + 1.f); j0 = edge_index[e0]; }
        if (e1 < E) { C1 = 0.5f * (__cosf(dist[e1] * PI_OVER_CUTOFF) + 1.f); j1 = edge_index[e1]; }

        // ================= GEMM1: acc1 = emb @ w1^T (K=64 padded) ==========
        float acc1[16][4];
        #pragma unroll
        for (int nt = 0; nt < 16; nt++)
            #pragma unroll
            for (int q = 0; q < 4; q++) acc1[nt][q] = 0.f;

        const float* eb = (const float*)(smw + embW + buf * EMBBUF);
        #pragma unroll
        for (int s = 0; s < 4; s++) {
            uint32_t a[4];
            if (s < 3) {
                int k0 = s * 16 + 2 * t;
                float2 p0 = *(const float2*)(eb + g * STE + k0);
                float2 p1 = *(const float2*)(eb + (g + 8) * STE + k0);
                float2 p2 = *(const float2*)(eb + g * STE + k0 + 8);
                float2 p3 = *(const float2*)(eb + (g + 8) * STE + k0 + 8);
                a[0] = cvt2(p0.x, p0.y); a[1] = cvt2(p1.x, p1.y);
                a[2] = cvt2(p2.x, p2.y); a[3] = cvt2(p3.x, p3.y);
            } else {
                // k = 48 + 2t (valid only t==0: k 48,49); k+8 all >= 50 -> 0
                if (t == 0) {
                    float2 p0 = *(const float2*)(eb + g * STE + 48);
                    float2 p1 = *(const float2*)(eb + (g + 8) * STE + 48);
                    a[0] = cvt2(p0.x, p0.y); a[1] = cvt2(p1.x, p1.y);
                } else { a[0] = 0; a[1] = 0; }
                a[2] = 0; a[3] = 0;
            }
            const uint32_t kb = (uint32_t)(s * 8) * 4u;
            #pragma unroll
            for (int np = 0; np < 8; np++) {
                uint32_t b0, b1, b2, b3;
                ldm_x4(b0, b1, b2, b3, w1B + kb + (uint32_t)(np * 16 * ST1) * 4u);
                uint32_t be[2] = { b0, b2 };
                uint32_t bo[2] = { b1, b3 };
                mma16816(acc1[2 * np],     a, be);
                mma16816(acc1[2 * np + 1], a, bo);
            }
        }

        // ---- h = softplus(acc1 + b1) - ln2 -> fp16 A-fragments (registers) ----
        // a2[s] is exactly the m16n8k16 A fragment for k-chunk 16s..16s+15.
        uint32_t a2[8][4];
        #pragma unroll
        for (int s = 0; s < 8; s++) {
            int f0 = 16 * s + 2 * t;
            float2 ba = *(const float2*)(b1f + f0);
            float2 bc = *(const float2*)(b1f + f0 + 8);
            a2[s][0] = cvt2(softplus_fast(acc1[2 * s][0] + ba.x) - SHIFT_LN2,
                            softplus_fast(acc1[2 * s][1] + ba.y) - SHIFT_LN2);
            a2[s][1] = cvt2(softplus_fast(acc1[2 * s][2] + ba.x) - SHIFT_LN2,
                            softplus_fast(acc1[2 * s][3] + ba.y) - SHIFT_LN2);
            a2[s][2] = cvt2(softplus_fast(acc1[2 * s + 1][0] + bc.x) - SHIFT_LN2,
                            softplus_fast(acc1[2 * s + 1][1] + bc.y) - SHIFT_LN2);
            a2[s][3] = cvt2(softplus_fast(acc1[2 * s + 1][2] + bc.x) - SHIFT_LN2,
                            softplus_fast(acc1[2 * s + 1][3] + bc.y) - SHIFT_LN2);
        }

        // ============ GEMM2 + epilogue, in two 64-feat halves ==============
        #pragma unroll
        for (int half = 0; half < 2; half++) {
            float acc2[8][4];
            #pragma unroll
            for (int nt = 0; nt < 8; nt++)
                #pragma unroll
                for (int q = 0; q < 4; q++) acc2[nt][q] = 0.f;

            #pragma unroll
            for (int s = 0; s < 8; s++) {
                const uint32_t kb = (uint32_t)(s * 8) * 4u;
                #pragma unroll
                for (int np = 0; np < 4; np++) {
                    uint32_t b0, b1, b2, b3;
                    ldm_x4(b0, b1, b2, b3,
                           w2B + kb + (uint32_t)((half * 64 + np * 16) * ST2) * 4u);
                    uint32_t be[2] = { b0, b2 };
                    uint32_t bo[2] = { b1, b3 };
                    mma16816(acc2[2 * np],     a2[s], be);
                    mma16816(acc2[2 * np + 1], a2[s], bo);
                }
            }

            // ---- epilogue: (acc2 + b2) * C * vl[j] -> out ----
            #pragma unroll
            for (int nt = 0; nt < 8; nt++) {
                int f = half * 64 + 8 * nt + 2 * t;
                float2 bb = *(const float2*)(b2f + f);
                if (e0 < E) {
                    float2 vv = *(const float2*)(g_vl + (size_t)j0 * 128 + f);
                    float2 o;
                    o.x = (acc2[nt][0] + bb.x) * C0 * vv.x;
                    o.y = (acc2[nt][1] + bb.y) * C0 * vv.y;
                    *(float2*)(out + (size_t)e0 * 128 + f) = o;
                }
                if (e1 < E) {
                    float2 vv = *(const float2*)(g_vl + (size_t)j1 * 128 + f);
                    float2 o;
                    o.x = (acc2[nt][2] + bb.x) * C1 * vv.x;
                    o.y = (acc2[nt][3] + bb.y) * C1 * vv.y;
                    *(float2*)(out + (size_t)e1 * 128 + f) = o;
                }
            }
        }
        buf ^= 1;
    }
}

// ---------------------------------------------------------------------------
extern "C" void kernel_launch(void* const* d_in, const int* in_sizes, int n_in,
                              void* d_out, int out_size)
{
    const float* v          = (const float*)d_in[0];
    const float* dist       = (const float*)d_in[1];
    const float* dist_emb   = (const float*)d_in[2];
    const int*   edge_index = (const int*)d_in[3];   // int32 [2][E]
    const float* lin_w      = (const float*)d_in[4];
    const float* mlp1_w     = (const float*)d_in[5];
    const float* mlp1_b     = (const float*)d_in[6];
    const float* mlp2_w     = (const float*)d_in[7];
    const float* mlp2_b     = (const float*)d_in[8];
    float*       out        = (float*)d_out;

    const int N = in_sizes[0] / 128;
    const int E = in_sizes[1];
    const int ngroups = (E + 15) / 16;

    const size_t smemA = (size_t)(128 * 128 + 128 * 132) * sizeof(float);
    const size_t smemB = (size_t)SMEM_WORDS * 4;     // 109568 B

    cudaFuncSetAttribute(vl_kernel, cudaFuncAttributeMaxDynamicSharedMemorySize, (int)smemA);
    cudaFuncSetAttribute(edge_mma_kernel, cudaFuncAttributeMaxDynamicSharedMemorySize, (int)smemB);

    vl_kernel<<<(N + 127) / 128, 256, smemA>>>(v, lin_w, N);

    edge_mma_kernel<<<304, 256, smemB>>>(dist, dist_emb, edge_index,
                                         mlp1_w, mlp1_b, mlp2_w, mlp2_b,
                                         out, E, ngroups);
}